// round 11
// baseline (speedup 1.0000x reference)
#include <cuda_runtime.h>
#include <cuda_bf16.h>
#include <cstdint>

// Problem constants
#define Bb    8
#define Tseq  2048
#define Cdim  1024
#define Hdim  64
#define BT    (Bb * Tseq)
#define QSCALE (0.125f * 1.44269504089f)   // H^-0.5 * log2(e): base-2 softmax
#define QT_N  32      // number of 64-row q tiles per batch
#define CHSUB 8       // kv subtiles (of 64) per chunk
#define MAXCH 4       // max chunks per q tile

// Scratch (device globals — no allocation allowed)
__device__ __align__(128) __nv_bfloat16 g_qh[BT * Hdim], g_ql[BT * Hdim];
__device__ __align__(128) __nv_bfloat16 g_kh[BT * Hdim], g_kl[BT * Hdim];
__device__ __align__(128) __nv_bfloat16 g_vh[BT * Hdim], g_vl[BT * Hdim];
__device__ __align__(128) __nv_bfloat16 g_bh[192 * Cdim], g_bl[192 * Cdim];
// attention partials
__device__ float g_pO[(size_t)Bb * QT_N * MAXCH * 64 * 64];
__device__ float g_pm[Bb * QT_N * MAXCH * 64];
__device__ float g_pl[Bb * QT_N * MAXCH * 64];

// ===========================================================================
// Generic-PTX tensor helpers (sm_80+ ISA)
// ===========================================================================
#define CP_ASYNC16(smem_u32, gptr) \
    asm volatile("cp.async.cg.shared.global [%0], [%1], 16;" \
                 :: "r"(smem_u32), "l"(gptr) : "memory")
#define CP_COMMIT() asm volatile("cp.async.commit_group;" ::: "memory")
#define CP_WAIT(N)  asm volatile("cp.async.wait_group %0;" :: "n"(N) : "memory")

#define LDMATRIX_X4(r0, r1, r2, r3, addr) \
    asm volatile("ldmatrix.sync.aligned.m8n8.x4.shared.b16 {%0,%1,%2,%3}, [%4];" \
                 : "=r"(r0), "=r"(r1), "=r"(r2), "=r"(r3) : "r"(addr))

#define LDMATRIX_X4_TRANS(r0, r1, r2, r3, addr) \
    asm volatile("ldmatrix.sync.aligned.m8n8.x4.trans.shared.b16 {%0,%1,%2,%3}, [%4];" \
                 : "=r"(r0), "=r"(r1), "=r"(r2), "=r"(r3) : "r"(addr))

// non-volatile — pure register op; data deps order it, ptxas may schedule
#define MMA_BF16(d, a, b0, b1) \
    asm("mma.sync.aligned.m16n8k16.row.col.f32.bf16.bf16.f32 " \
        "{%0,%1,%2,%3}, {%4,%5,%6,%7}, {%8,%9}, {%0,%1,%2,%3};" \
        : "+f"((d)[0]), "+f"((d)[1]), "+f"((d)[2]), "+f"((d)[3]) \
        : "r"((a)[0]), "r"((a)[1]), "r"((a)[2]), "r"((a)[3]), \
          "r"(b0), "r"(b1))

__device__ __forceinline__ uint32_t smem_to_u32(const void* p) {
    uint32_t a;
    asm("{ .reg .u64 t; cvta.to.shared.u64 t, %1; cvt.u32.u64 %0, t; }" : "=r"(a) : "l"(p));
    return a;
}

__device__ __forceinline__ void split2(float x, float y, uint32_t& hi, uint32_t& lo) {
    __nv_bfloat16 hx = __float2bfloat16(x), hy = __float2bfloat16(y);
    __nv_bfloat162 h2 = __halves2bfloat162(hx, hy);
    hi = *(uint32_t*)&h2;
    __nv_bfloat162 l2 = __halves2bfloat162(
        __float2bfloat16(x - __bfloat162float(hx)),
        __float2bfloat16(y - __bfloat162float(hy)));
    lo = *(uint32_t*)&l2;
}

// ===========================================================================
// Kernel 0: pack + split weights into g_bh/g_bl  [192][1024] K-major
// ===========================================================================
__global__ __launch_bounds__(256) void pack_w_kernel(
    const float* __restrict__ wq, const float* __restrict__ wk, const float* __restrict__ wv)
{
    int idx = blockIdx.x * 256 + threadIdx.x;
    int n = idx >> 10;
    int k = idx & 1023;
    const float* w = (n < 64) ? wq : (n < 128) ? wk : wv;
    float v  = w[k * Hdim + (n & 63)];
    __nv_bfloat16 hi = __float2bfloat16(v);
    g_bh[idx] = hi;
    g_bl[idx] = __float2bfloat16(v - __bfloat162float(hi));
}

// ===========================================================================
// Kernel 1: projection GEMM, CTA tile 128m x 96n (N split in halves),
// 256 threads, 1 CTA/SM, grid=256 for full-chip packing. Adjacent CTA pairs
// share the x tile (L2 reuse). fp32 x cp.async'd raw, split in-kernel.
// 8 warps as 4m x 2n (warp tile 32x48). 3-pass MMA order.
// ===========================================================================
#define ROWB144    144
#define PAH_OFF    0                       // 2 x 18432
#define PAL_OFF    36864                   // 2 x 18432
#define PBH_OFF    73728                   // 2 x 13824
#define PBL_OFF    101376                  // 2 x 13824
#define PRAW_OFF   129024                  // 32768
#define PROJ_SMEM  161792
#define PA_STG     18432
#define PB_STG     13824
#define NCHUNK     (Cdim / 64)             // 16

__global__ __launch_bounds__(256, 1) void proj_mma_kernel(const float* __restrict__ x)
{
    extern __shared__ char smem[];
    const uint32_t sb = smem_to_u32(smem);
    const int tid  = threadIdx.x;
    const int wid  = tid >> 5;
    const int lane = tid & 31;
    const int row0 = (blockIdx.x >> 1) * 128;
    const int half = blockIdx.x & 1;        // N half: cols [half*96, half*96+96)

    const int wm = wid >> 1;                // 0..3 -> 32 rows each
    const int wn = wid & 1;                 // 0..1 -> 48 cols each

    float acc[2][6][4];
    #pragma unroll
    for (int i = 0; i < 2; i++)
        #pragma unroll
        for (int j = 0; j < 6; j++)
            #pragma unroll
            for (int r = 0; r < 4; r++) acc[i][j][r] = 0.f;

    auto issue_chunk = [&](int c) {
        const int k0 = c * 64;
        const int s  = c & 1;
        // raw x: 128 rows x 256 B -> 2048 segs, 8/thread
        #pragma unroll
        for (int t = 0; t < 8; t++) {
            int seg = tid + t * 256;
            int r = seg >> 4, o = seg & 15;
            CP_ASYNC16(sb + PRAW_OFF + r * 256 + o * 16,
                       &x[(size_t)(row0 + r) * Cdim + k0 + o * 4]);
        }
        // B hi/lo: 96 rows x 128 B each -> 768 segs per split, 3/thread
        #pragma unroll
        for (int t = 0; t < 3; t++) {
            int seg = tid + t * 256;
            int r = seg >> 3, o8 = seg & 7;
            size_t ge = (size_t)(half * 96 + r) * Cdim + k0 + o8 * 8;
            CP_ASYNC16(sb + PBH_OFF + s * PB_STG + r * ROWB144 + o8 * 16, &g_bh[ge]);
            CP_ASYNC16(sb + PBL_OFF + s * PB_STG + r * ROWB144 + o8 * 16, &g_bl[ge]);
        }
        CP_COMMIT();
    };

    issue_chunk(0);

    const int rsel = lane & 15;
    const int ksel = (lane < 16) ? 0 : 8;

    for (int c = 0; c < NCHUNK; c++) {
        const int s = c & 1;
        CP_WAIT(0);
        __syncthreads();

        // convert raw fp32 -> Ah/Al stage s  (8 float4 per thread)
        #pragma unroll
        for (int t = 0; t < 8; t++) {
            int seg = tid + t * 256;          // 0..2047
            int r = seg >> 4, kp = seg & 15;
            float4 v = *(const float4*)(smem + PRAW_OFF + r * 256 + kp * 16);
            uint32_t h0, l0, h1, l1;
            split2(v.x, v.y, h0, l0);
            split2(v.z, v.w, h1, l1);
            asm volatile("st.shared.v2.b32 [%0], {%1, %2};"
                         :: "r"(sb + PAH_OFF + s * PA_STG + r * ROWB144 + kp * 8),
                            "r"(h0), "r"(h1) : "memory");
            asm volatile("st.shared.v2.b32 [%0], {%1, %2};"
                         :: "r"(sb + PAL_OFF + s * PA_STG + r * ROWB144 + kp * 8),
                            "r"(l0), "r"(l1) : "memory");
        }
        __syncthreads();          // splits visible; raw buffer free

        if (c + 1 < NCHUNK) issue_chunk(c + 1);

        const uint32_t Ah = sb + PAH_OFF + s * PA_STG;
        const uint32_t Al = sb + PAL_OFF + s * PA_STG;
        const uint32_t Bh = sb + PBH_OFF + s * PB_STG;
        const uint32_t Bl = sb + PBL_OFF + s * PB_STG;

        #pragma unroll
        for (int kk = 0; kk < 4; kk++) {
            const uint32_t kb = (kk * 16 + ksel) * 2;
            uint32_t ah[2][4], al[2][4];
            #pragma unroll
            for (int i = 0; i < 2; i++) {
                uint32_t ro = (uint32_t)(wm * 32 + i * 16 + rsel) * ROWB144 + kb;
                LDMATRIX_X4(ah[i][0], ah[i][1], ah[i][2], ah[i][3], Ah + ro);
                LDMATRIX_X4(al[i][0], al[i][1], al[i][2], al[i][3], Al + ro);
            }
            uint32_t bh[3][4], bl[3][4];
            #pragma unroll
            for (int p = 0; p < 3; p++) {
                uint32_t ro = (uint32_t)(wn * 48 + p * 16 + rsel) * ROWB144 + kb;
                LDMATRIX_X4(bh[p][0], bh[p][1], bh[p][2], bh[p][3], Bh + ro);
                LDMATRIX_X4(bl[p][0], bl[p][1], bl[p][2], bl[p][3], Bl + ro);
            }
            // pass 1: hi * hi  (12 independent MMAs)
            #pragma unroll
            for (int i = 0; i < 2; i++)
                #pragma unroll
                for (int p = 0; p < 3; p++)
                    #pragma unroll
                    for (int h = 0; h < 2; h++)
                        MMA_BF16(acc[i][p * 2 + h], ah[i], bh[p][h], bh[p][h + 2]);
            // pass 2: hi * lo
            #pragma unroll
            for (int i = 0; i < 2; i++)
                #pragma unroll
                for (int p = 0; p < 3; p++)
                    #pragma unroll
                    for (int h = 0; h < 2; h++)
                        MMA_BF16(acc[i][p * 2 + h], ah[i], bl[p][h], bl[p][h + 2]);
            // pass 3: lo * hi
            #pragma unroll
            for (int i = 0; i < 2; i++)
                #pragma unroll
                for (int p = 0; p < 3; p++)
                    #pragma unroll
                    for (int h = 0; h < 2; h++)
                        MMA_BF16(acc[i][p * 2 + h], al[i], bh[p][h], bh[p][h + 2]);
        }
        __syncthreads();
    }

    // Epilogue: q -> scaled bf16 hi/lo; k, v -> bf16 hi/lo (natural [t][h])
    #pragma unroll
    for (int i = 0; i < 2; i++) {
        const int rA = row0 + wm * 32 + i * 16 + (lane >> 2);
        #pragma unroll
        for (int j = 0; j < 6; j++) {
            const int col = half * 96 + wn * 48 + j * 8 + (lane & 3) * 2;
            float v00 = acc[i][j][0], v01 = acc[i][j][1];
            float v10 = acc[i][j][2], v11 = acc[i][j][3];
            uint32_t hi, lo;
            const int h = col & 63;
            size_t o0 = (size_t)rA * Hdim + h;
            size_t o1 = (size_t)(rA + 8) * Hdim + h;
            if (col < 64) {
                split2(v00 * QSCALE, v01 * QSCALE, hi, lo);
                *(uint32_t*)&g_qh[o0] = hi; *(uint32_t*)&g_ql[o0] = lo;
                split2(v10 * QSCALE, v11 * QSCALE, hi, lo);
                *(uint32_t*)&g_qh[o1] = hi; *(uint32_t*)&g_ql[o1] = lo;
            } else if (col < 128) {
                split2(v00, v01, hi, lo);
                *(uint32_t*)&g_kh[o0] = hi; *(uint32_t*)&g_kl[o0] = lo;
                split2(v10, v11, hi, lo);
                *(uint32_t*)&g_kh[o1] = hi; *(uint32_t*)&g_kl[o1] = lo;
            } else {
                split2(v00, v01, hi, lo);
                *(uint32_t*)&g_vh[o0] = hi; *(uint32_t*)&g_vl[o0] = lo;
                split2(v10, v11, hi, lo);
                *(uint32_t*)&g_vh[o1] = hi; *(uint32_t*)&g_vl[o1] = lo;
            }
        }
    }
}

// ===========================================================================
// Kernel 2: flash-attention work units on mma.sync bf16 (base-2 softmax).
// Unit = (batch, qtile of 64 rows, kv-chunk of up to 8x64). 3-pass MMA order.
// ===========================================================================
#define ROWB   144
#define QH_OFF 0
#define QL_OFF 9216
#define STG_OFF 18432
#define STG_SZ  36864                       // Kh | Kl | Vh | Vl (9216 each)
#define ATTN_SMEM (STG_OFF + 2 * STG_SZ)    // 92160

__global__ __launch_bounds__(128) void attn_mma_kernel()
{
    extern __shared__ char smem[];
    const uint32_t sb = smem_to_u32(smem);
    const int tid  = threadIdx.x;
    const int w    = tid >> 5;
    const int lane = tid & 31;
    const int b    = blockIdx.y;

    // map blockIdx.x -> (qt, chunk), heavy qtiles first
    int u = blockIdx.x, qt = QT_N - 1, chunk = 0;
    for (;;) {
        int nc = (qt + CHSUB) >> 3;
        if (u < nc) { chunk = u; break; }
        u -= nc; qt--;
    }
    const int nsub = min(CHSUB, (qt + 1) - chunk * CHSUB);
    const int sub0 = chunk * CHSUB;
    const int q0   = qt * 64;

    // ---- stage Q (hi+lo) ----
    {
        const __nv_bfloat16* qhp = g_qh + ((size_t)(b * Tseq + q0)) * Hdim;
        const __nv_bfloat16* qlp = g_ql + ((size_t)(b * Tseq + q0)) * Hdim;
        #pragma unroll
        for (int t = 0; t < 4; t++) {
            int seg = tid + t * 128;
            int r = seg >> 3, o = seg & 7;
            CP_ASYNC16(sb + QH_OFF + r * ROWB + o * 16, qhp + r * 64 + o * 8);
            CP_ASYNC16(sb + QL_OFF + r * ROWB + o * 16, qlp + r * 64 + o * 8);
        }
        CP_COMMIT();
    }

    auto stage = [&](int s, int buf) {
        const uint32_t o = sb + STG_OFF + (uint32_t)buf * STG_SZ;
        const size_t gbase = ((size_t)(b * Tseq + s * 64)) * Hdim;
        #pragma unroll
        for (int t = 0; t < 4; t++) {
            int seg = tid + t * 128;
            int r = seg >> 3, c = seg & 7;
            size_t ge = gbase + r * 64 + c * 8;
            CP_ASYNC16(o + r * ROWB + c * 16,         &g_kh[ge]);
            CP_ASYNC16(o + 9216 + r * ROWB + c * 16,  &g_kl[ge]);
            CP_ASYNC16(o + 18432 + r * ROWB + c * 16, &g_vh[ge]);
            CP_ASYNC16(o + 27648 + r * ROWB + c * 16, &g_vl[ge]);
        }
        CP_COMMIT();
    };

    stage(sub0, 0);
    if (nsub > 1) stage(sub0 + 1, 1);

    const int rsel  = lane & 15;
    const int ksel2 = (lane < 16) ? 0 : 16;
    const int vkv  = ((lane >> 4) & 1) * 8 + (lane & 7);
    const int vh16 = ((lane >> 3) & 1) * 16;

    if (nsub > 1) { CP_WAIT(1); } else { CP_WAIT(0); }
    __syncthreads();

    uint32_t qfh[4][4], qfl[4][4];
    #pragma unroll
    for (int ks = 0; ks < 4; ks++) {
        uint32_t ro = sb + (uint32_t)(w * 16 + rsel) * ROWB + ks * 32 + ksel2;
        LDMATRIX_X4(qfh[ks][0], qfh[ks][1], qfh[ks][2], qfh[ks][3], ro + QH_OFF);
        LDMATRIX_X4(qfl[ks][0], qfl[ks][1], qfl[ks][2], qfl[ks][3], ro + QL_OFF);
    }

    float m0 = -1e30f, m1 = -1e30f, l0 = 0.f, l1 = 0.f;
    float O[8][4];
    #pragma unroll
    for (int f = 0; f < 8; f++)
        #pragma unroll
        for (int r = 0; r < 4; r++) O[f][r] = 0.f;

    const int gr  = lane >> 2;
    const int gc2 = (lane & 3) * 2;

    for (int i = 0; i < nsub; i++) {
        if (i > 0) {
            if (i + 1 < nsub) CP_WAIT(1); else CP_WAIT(0);
            __syncthreads();
        }
        const uint32_t kb = sb + STG_OFF + (uint32_t)(i & 1) * STG_SZ;
        const int sglob = sub0 + i;

        // ---- S = Q K^T (3-way split, 3-pass order) ----
        float S[8][4];
        #pragma unroll
        for (int f = 0; f < 8; f++)
            #pragma unroll
            for (int r = 0; r < 4; r++) S[f][r] = 0.f;

        #pragma unroll
        for (int ks = 0; ks < 4; ks++) {
            uint32_t bh[4][4], bl[4][4];
            #pragma unroll
            for (int nt = 0; nt < 4; nt++) {
                uint32_t ro = kb + (uint32_t)(nt * 16 + rsel) * ROWB + ks * 32 + ksel2;
                LDMATRIX_X4(bh[nt][0], bh[nt][1], bh[nt][2], bh[nt][3], ro);
                LDMATRIX_X4(bl[nt][0], bl[nt][1], bl[nt][2], bl[nt][3], ro + 9216);
            }
            #pragma unroll
            for (int nt = 0; nt < 4; nt++)
                #pragma unroll
                for (int h = 0; h < 2; h++)
                    MMA_BF16(S[nt * 2 + h], qfh[ks], bh[nt][h], bh[nt][h + 2]);
            #pragma unroll
            for (int nt = 0; nt < 4; nt++)
                #pragma unroll
                for (int h = 0; h < 2; h++)
                    MMA_BF16(S[nt * 2 + h], qfh[ks], bl[nt][h], bl[nt][h + 2]);
            #pragma unroll
            for (int nt = 0; nt < 4; nt++)
                #pragma unroll
                for (int h = 0; h < 2; h++)
                    MMA_BF16(S[nt * 2 + h], qfl[ks], bh[nt][h], bh[nt][h + 2]);
        }

        // ---- causal mask (diagonal subtile only) ----
        if (sglob == qt) {
            const int r0 = q0 + w * 16 + gr;
            #pragma unroll
            for (int f = 0; f < 8; f++) {
                const int c = q0 + f * 8 + gc2;
                if (c     > r0)     S[f][0] = -1e30f;
                if (c + 1 > r0)     S[f][1] = -1e30f;
                if (c     > r0 + 8) S[f][2] = -1e30f;
                if (c + 1 > r0 + 8) S[f][3] = -1e30f;
            }
        }

        // ---- online softmax (base 2) ----
        float mx0 = -1e30f, mx1 = -1e30f;
        #pragma unroll
        for (int f = 0; f < 8; f++) {
            mx0 = fmaxf(mx0, fmaxf(S[f][0], S[f][1]));
            mx1 = fmaxf(mx1, fmaxf(S[f][2], S[f][3]));
        }
        mx0 = fmaxf(mx0, __shfl_xor_sync(0xffffffffu, mx0, 1));
        mx0 = fmaxf(mx0, __shfl_xor_sync(0xffffffffu, mx0, 2));
        mx1 = fmaxf(mx1, __shfl_xor_sync(0xffffffffu, mx1, 1));
        mx1 = fmaxf(mx1, __shfl_xor_sync(0xffffffffu, mx1, 2));
        const float mn0 = fmaxf(m0, mx0), mn1 = fmaxf(m1, mx1);
        const float a0 = exp2f(m0 - mn0), a1 = exp2f(m1 - mn1);
        float s0 = 0.f, s1 = 0.f;
        #pragma unroll
        for (int f = 0; f < 8; f++) {
            S[f][0] = exp2f(S[f][0] - mn0);
            S[f][1] = exp2f(S[f][1] - mn0);
            S[f][2] = exp2f(S[f][2] - mn1);
            S[f][3] = exp2f(S[f][3] - mn1);
            s0 += S[f][0] + S[f][1];
            s1 += S[f][2] + S[f][3];
        }
        s0 += __shfl_xor_sync(0xffffffffu, s0, 1);
        s0 += __shfl_xor_sync(0xffffffffu, s0, 2);
        s1 += __shfl_xor_sync(0xffffffffu, s1, 1);
        s1 += __shfl_xor_sync(0xffffffffu, s1, 2);
        l0 = l0 * a0 + s0;
        l1 = l1 * a1 + s1;
        m0 = mn0; m1 = mn1;
        #pragma unroll
        for (int f = 0; f < 8; f++) {
            O[f][0] *= a0; O[f][1] *= a0;
            O[f][2] *= a1; O[f][3] *= a1;
        }

        // ---- O += P V (3-way split, 3-pass order); V via ldmatrix.trans ----
        #pragma unroll
        for (int ks = 0; ks < 4; ks++) {
            uint32_t pha[4], pla[4];
            split2(S[2 * ks][0],     S[2 * ks][1],     pha[0], pla[0]);
            split2(S[2 * ks][2],     S[2 * ks][3],     pha[1], pla[1]);
            split2(S[2 * ks + 1][0], S[2 * ks + 1][1], pha[2], pla[2]);
            split2(S[2 * ks + 1][2], S[2 * ks + 1][3], pha[3], pla[3]);
            uint32_t vh[4][4], vl[4][4];
            #pragma unroll
            for (int ht = 0; ht < 4; ht++) {
                uint32_t ro = kb + 18432u + (uint32_t)(ks * 16 + vkv) * ROWB + ht * 32 + vh16;
                LDMATRIX_X4_TRANS(vh[ht][0], vh[ht][1], vh[ht][2], vh[ht][3], ro);
                LDMATRIX_X4_TRANS(vl[ht][0], vl[ht][1], vl[ht][2], vl[ht][3], ro + 9216);
            }
            #pragma unroll
            for (int ht = 0; ht < 4; ht++)
                #pragma unroll
                for (int h = 0; h < 2; h++)
                    MMA_BF16(O[ht * 2 + h], pha, vh[ht][h], vh[ht][h + 2]);
            #pragma unroll
            for (int ht = 0; ht < 4; ht++)
                #pragma unroll
                for (int h = 0; h < 2; h++)
                    MMA_BF16(O[ht * 2 + h], pha, vl[ht][h], vl[ht][h + 2]);
            #pragma unroll
            for (int ht = 0; ht < 4; ht++)
                #pragma unroll
                for (int h = 0; h < 2; h++)
                    MMA_BF16(O[ht * 2 + h], pla, vh[ht][h], vh[ht][h + 2]);
        }

        __syncthreads();
        if (i + 2 < nsub) stage(sub0 + i + 2, i & 1);
    }

    // ---- epilogue: write partials (m in log2 units) ----
    {
        const size_t base = ((size_t)((b * QT_N + qt) * MAXCH + chunk)) * 4096;
        const int r0 = w * 16 + gr;
        #pragma unroll
        for (int f = 0; f < 8; f++) {
            const int h = f * 8 + gc2;
            *(float2*)&g_pO[base + (size_t)r0 * 64 + h]       = make_float2(O[f][0], O[f][1]);
            *(float2*)&g_pO[base + (size_t)(r0 + 8) * 64 + h] = make_float2(O[f][2], O[f][3]);
        }
        if ((lane & 3) == 0) {
            const size_t sbs = (size_t)((b * QT_N + qt) * MAXCH + chunk) * 64;
            g_pm[sbs + r0]     = m0;  g_pm[sbs + r0 + 8] = m1;
            g_pl[sbs + r0]     = l0;  g_pl[sbs + r0 + 8] = l1;
        }
    }
}

// ===========================================================================
// Kernel 3: combine partials -> final output (predicated prefetch, MLP=4)
// ===========================================================================
__global__ __launch_bounds__(256) void combine_kernel(float* __restrict__ out)
{
    int idx = blockIdx.x * 256 + threadIdx.x;
    int h4  = idx & 15;
    int q   = (Tseq - 1) - ((idx >> 4) & (Tseq - 1));   // heavy q rows first
    int b   = idx >> 15;
    int qt  = q >> 6;
    int row = q & 63;
    int nc  = (qt + CHSUB) >> 3;

    const size_t sbs = (size_t)(b * QT_N + qt) * MAXCH * 64 + row;
    const size_t ob  = (size_t)(b * QT_N + qt) * MAXCH * 4096 + (size_t)row * 64 + h4 * 4;

    float pm[MAXCH], pl[MAXCH];
    float4 p[MAXCH];
    #pragma unroll
    for (int c = 0; c < MAXCH; c++) {
        const bool v = c < nc;
        pm[c] = v ? g_pm[sbs + c * 64] : -1e30f;
        pl[c] = v ? g_pl[sbs + c * 64] : 0.f;
        p[c]  = v ? *(const float4*)&g_pO[ob + (size_t)c * 4096]
                  : make_float4(0.f, 0.f, 0.f, 0.f);
    }

    const float M = fmaxf(fmaxf(pm[0], pm[1]), fmaxf(pm[2], pm[3]));
    float L = 0.f, ox = 0.f, oy = 0.f, oz = 0.f, ow = 0.f;
    #pragma unroll
    for (int c = 0; c < MAXCH; c++) {
        const float wgt = exp2f(pm[c] - M);
        L += pl[c] * wgt;
        ox += wgt * p[c].x; oy += wgt * p[c].y;
        oz += wgt * p[c].z; ow += wgt * p[c].w;
    }
    const float inv = 1.0f / L;
    *(float4*)&out[((size_t)(b * Tseq + q)) * Hdim + h4 * 4] =
        make_float4(ox * inv, oy * inv, oz * inv, ow * inv);
}

// ===========================================================================
extern "C" void kernel_launch(void* const* d_in, const int* in_sizes, int n_in,
                              void* d_out, int out_size)
{
    const float* x  = (const float*)d_in[0];
    const float* wq = (const float*)d_in[1];
    const float* wk = (const float*)d_in[2];
    const float* wv = (const float*)d_in[3];
    float* out = (float*)d_out;

    cudaFuncSetAttribute(proj_mma_kernel, cudaFuncAttributeMaxDynamicSharedMemorySize,
                         PROJ_SMEM);
    cudaFuncSetAttribute(attn_mma_kernel, cudaFuncAttributeMaxDynamicSharedMemorySize,
                         ATTN_SMEM);

    pack_w_kernel<<<(192 * Cdim) / 256, 256>>>(wq, wk, wv);
    proj_mma_kernel<<<(BT / 128) * 2, 256, PROJ_SMEM>>>(x);
    attn_mma_kernel<<<dim3(80, Bb), 128, ATTN_SMEM>>>();
    combine_kernel<<<(Bb * Tseq * 16) / 256, 256>>>(out);
}

// round 12
// speedup vs baseline: 1.0847x; 1.0847x over previous
#include <cuda_runtime.h>
#include <cuda_bf16.h>
#include <cstdint>

// Problem constants
#define Bb    8
#define Tseq  2048
#define Cdim  1024
#define Hdim  64
#define BT    (Bb * Tseq)
#define QSCALE (0.125f * 1.44269504089f)   // H^-0.5 * log2(e): base-2 softmax
#define QT_N  32      // number of 64-row q tiles per batch
#define CHSUB 8       // kv subtiles (of 64) per chunk
#define MAXCH 4       // max chunks per q tile

// Scratch (device globals — no allocation allowed)
__device__ __align__(128) __nv_bfloat16 g_qh[BT * Hdim], g_ql[BT * Hdim];
__device__ __align__(128) __nv_bfloat16 g_kh[BT * Hdim], g_kl[BT * Hdim];
__device__ __align__(128) __nv_bfloat16 g_vh[BT * Hdim], g_vl[BT * Hdim];
__device__ __align__(128) __nv_bfloat16 g_bh[192 * Cdim], g_bl[192 * Cdim];
// attention partials
__device__ float g_pO[(size_t)Bb * QT_N * MAXCH * 64 * 64];
__device__ float g_pm[Bb * QT_N * MAXCH * 64];
__device__ float g_pl[Bb * QT_N * MAXCH * 64];

// ===========================================================================
// Generic-PTX tensor helpers (sm_80+ ISA)
// ===========================================================================
#define CP_ASYNC16(smem_u32, gptr) \
    asm volatile("cp.async.cg.shared.global [%0], [%1], 16;" \
                 :: "r"(smem_u32), "l"(gptr) : "memory")
#define CP_COMMIT() asm volatile("cp.async.commit_group;" ::: "memory")
#define CP_WAIT(N)  asm volatile("cp.async.wait_group %0;" :: "n"(N) : "memory")

#define LDMATRIX_X4(r0, r1, r2, r3, addr) \
    asm volatile("ldmatrix.sync.aligned.m8n8.x4.shared.b16 {%0,%1,%2,%3}, [%4];" \
                 : "=r"(r0), "=r"(r1), "=r"(r2), "=r"(r3) : "r"(addr))

#define LDMATRIX_X4_TRANS(r0, r1, r2, r3, addr) \
    asm volatile("ldmatrix.sync.aligned.m8n8.x4.trans.shared.b16 {%0,%1,%2,%3}, [%4];" \
                 : "=r"(r0), "=r"(r1), "=r"(r2), "=r"(r3) : "r"(addr))

// non-volatile — pure register op; data deps order it, ptxas may schedule
#define MMA_BF16(d, a, b0, b1) \
    asm("mma.sync.aligned.m16n8k16.row.col.f32.bf16.bf16.f32 " \
        "{%0,%1,%2,%3}, {%4,%5,%6,%7}, {%8,%9}, {%0,%1,%2,%3};" \
        : "+f"((d)[0]), "+f"((d)[1]), "+f"((d)[2]), "+f"((d)[3]) \
        : "r"((a)[0]), "r"((a)[1]), "r"((a)[2]), "r"((a)[3]), \
          "r"(b0), "r"(b1))

__device__ __forceinline__ uint32_t smem_to_u32(const void* p) {
    uint32_t a;
    asm("{ .reg .u64 t; cvta.to.shared.u64 t, %1; cvt.u32.u64 %0, t; }" : "=r"(a) : "l"(p));
    return a;
}

__device__ __forceinline__ void split2(float x, float y, uint32_t& hi, uint32_t& lo) {
    __nv_bfloat16 hx = __float2bfloat16(x), hy = __float2bfloat16(y);
    __nv_bfloat162 h2 = __halves2bfloat162(hx, hy);
    hi = *(uint32_t*)&h2;
    __nv_bfloat162 l2 = __halves2bfloat162(
        __float2bfloat16(x - __bfloat162float(hx)),
        __float2bfloat16(y - __bfloat162float(hy)));
    lo = *(uint32_t*)&l2;
}

// ===========================================================================
// Kernel 0: pack + split weights into g_bh/g_bl  [192][1024] K-major
// ===========================================================================
__global__ __launch_bounds__(256) void pack_w_kernel(
    const float* __restrict__ wq, const float* __restrict__ wk, const float* __restrict__ wv)
{
    int idx = blockIdx.x * 256 + threadIdx.x;
    int n = idx >> 10;
    int k = idx & 1023;
    const float* w = (n < 64) ? wq : (n < 128) ? wk : wv;
    float v  = w[k * Hdim + (n & 63)];
    __nv_bfloat16 hi = __float2bfloat16(v);
    g_bh[idx] = hi;
    g_bl[idx] = __float2bfloat16(v - __bfloat162float(hi));
}

// ===========================================================================
// Kernel 1: projection GEMM (round-9 configuration — empirical optimum).
// CTA tile 128m x 192n, 256 threads, grid=128. fp32 x cp.async'd raw and
// split to bf16 hi/lo in-kernel. 3-pass MMA order (hi*hi | hi*lo | lo*hi).
// ===========================================================================
#define ROWB144    144
#define AH_OFF     0                      // 2 x 18432
#define AL_OFF     36864                  // 2 x 18432
#define BH_OFF     73728                  // 2 x 27648
#define BL_OFF     129024                 // 2 x 27648
#define RAW_OFF    184320                 // 32768
#define PROJ_SMEM  217088
#define A_STG      18432
#define B_STG      27648
#define NCHUNK     (Cdim / 64)            // 16

__global__ __launch_bounds__(256, 1) void proj_mma_kernel(const float* __restrict__ x)
{
    extern __shared__ char smem[];
    const uint32_t sb = smem_to_u32(smem);
    const int tid  = threadIdx.x;
    const int wid  = tid >> 5;
    const int lane = tid & 31;
    const int row0 = blockIdx.x * 128;

    const int wm = wid >> 2;
    const int wn = wid & 3;

    float acc[4][6][4];
    #pragma unroll
    for (int i = 0; i < 4; i++)
        #pragma unroll
        for (int j = 0; j < 6; j++)
            #pragma unroll
            for (int r = 0; r < 4; r++) acc[i][j][r] = 0.f;

    auto issue_chunk = [&](int c) {
        const int k0 = c * 64;
        const int s  = c & 1;
        #pragma unroll
        for (int t = 0; t < 8; t++) {
            int seg = tid + t * 256;
            int r = seg >> 4, o = seg & 15;
            CP_ASYNC16(sb + RAW_OFF + r * 256 + o * 16,
                       &x[(size_t)(row0 + r) * Cdim + k0 + o * 4]);
        }
        #pragma unroll
        for (int t = 0; t < 6; t++) {
            int seg = tid + t * 256;
            int r = seg >> 3, o8 = seg & 7;
            size_t ge = (size_t)r * Cdim + k0 + o8 * 8;
            CP_ASYNC16(sb + BH_OFF + s * B_STG + r * ROWB144 + o8 * 16, &g_bh[ge]);
            CP_ASYNC16(sb + BL_OFF + s * B_STG + r * ROWB144 + o8 * 16, &g_bl[ge]);
        }
        CP_COMMIT();
    };

    issue_chunk(0);

    const int rsel = lane & 15;
    const int ksel = (lane < 16) ? 0 : 8;

    for (int c = 0; c < NCHUNK; c++) {
        const int s = c & 1;
        CP_WAIT(0);
        __syncthreads();

        // convert raw fp32 -> Ah/Al stage s  (8 float4 per thread)
        #pragma unroll
        for (int t = 0; t < 8; t++) {
            int seg = tid + t * 256;          // 0..2047
            int r = seg >> 4, kp = seg & 15;
            float4 v = *(const float4*)(smem + RAW_OFF + r * 256 + kp * 16);
            uint32_t h0, l0, h1, l1;
            split2(v.x, v.y, h0, l0);
            split2(v.z, v.w, h1, l1);
            asm volatile("st.shared.v2.b32 [%0], {%1, %2};"
                         :: "r"(sb + AH_OFF + s * A_STG + r * ROWB144 + kp * 8),
                            "r"(h0), "r"(h1) : "memory");
            asm volatile("st.shared.v2.b32 [%0], {%1, %2};"
                         :: "r"(sb + AL_OFF + s * A_STG + r * ROWB144 + kp * 8),
                            "r"(l0), "r"(l1) : "memory");
        }
        __syncthreads();                       // splits visible; raw buffer free

        if (c + 1 < NCHUNK) issue_chunk(c + 1);

        const uint32_t Ah = sb + AH_OFF + s * A_STG;
        const uint32_t Al = sb + AL_OFF + s * A_STG;
        const uint32_t Bh = sb + BH_OFF + s * B_STG;
        const uint32_t Bl = sb + BL_OFF + s * B_STG;

        #pragma unroll
        for (int kk = 0; kk < 4; kk++) {
            const uint32_t kb = (kk * 16 + ksel) * 2;
            uint32_t ah[4][4], al[4][4];
            #pragma unroll
            for (int i = 0; i < 4; i++) {
                uint32_t ro = (uint32_t)(wm * 64 + i * 16 + rsel) * ROWB144 + kb;
                LDMATRIX_X4(ah[i][0], ah[i][1], ah[i][2], ah[i][3], Ah + ro);
                LDMATRIX_X4(al[i][0], al[i][1], al[i][2], al[i][3], Al + ro);
            }
            uint32_t bh[3][4], bl[3][4];
            #pragma unroll
            for (int p = 0; p < 3; p++) {
                uint32_t ro = (uint32_t)(wn * 48 + p * 16 + rsel) * ROWB144 + kb;
                LDMATRIX_X4(bh[p][0], bh[p][1], bh[p][2], bh[p][3], Bh + ro);
                LDMATRIX_X4(bl[p][0], bl[p][1], bl[p][2], bl[p][3], Bl + ro);
            }
            // pass 1: hi * hi  (24 independent MMAs)
            #pragma unroll
            for (int i = 0; i < 4; i++)
                #pragma unroll
                for (int p = 0; p < 3; p++)
                    #pragma unroll
                    for (int h = 0; h < 2; h++)
                        MMA_BF16(acc[i][p * 2 + h], ah[i], bh[p][h], bh[p][h + 2]);
            // pass 2: hi * lo
            #pragma unroll
            for (int i = 0; i < 4; i++)
                #pragma unroll
                for (int p = 0; p < 3; p++)
                    #pragma unroll
                    for (int h = 0; h < 2; h++)
                        MMA_BF16(acc[i][p * 2 + h], ah[i], bl[p][h], bl[p][h + 2]);
            // pass 3: lo * hi
            #pragma unroll
            for (int i = 0; i < 4; i++)
                #pragma unroll
                for (int p = 0; p < 3; p++)
                    #pragma unroll
                    for (int h = 0; h < 2; h++)
                        MMA_BF16(acc[i][p * 2 + h], al[i], bh[p][h], bh[p][h + 2]);
        }
        __syncthreads();
    }

    // Epilogue: q -> scaled (by H^-0.5 * log2e) bf16 hi/lo; k, v -> bf16 hi/lo
    #pragma unroll
    for (int i = 0; i < 4; i++) {
        const int rA = row0 + wm * 64 + i * 16 + (lane >> 2);
        #pragma unroll
        for (int j = 0; j < 6; j++) {
            const int col = wn * 48 + j * 8 + (lane & 3) * 2;
            float v00 = acc[i][j][0], v01 = acc[i][j][1];
            float v10 = acc[i][j][2], v11 = acc[i][j][3];
            uint32_t hi, lo;
            const int h = col & 63;
            size_t o0 = (size_t)rA * Hdim + h;
            size_t o1 = (size_t)(rA + 8) * Hdim + h;
            if (col < 64) {
                split2(v00 * QSCALE, v01 * QSCALE, hi, lo);
                *(uint32_t*)&g_qh[o0] = hi; *(uint32_t*)&g_ql[o0] = lo;
                split2(v10 * QSCALE, v11 * QSCALE, hi, lo);
                *(uint32_t*)&g_qh[o1] = hi; *(uint32_t*)&g_ql[o1] = lo;
            } else if (col < 128) {
                split2(v00, v01, hi, lo);
                *(uint32_t*)&g_kh[o0] = hi; *(uint32_t*)&g_kl[o0] = lo;
                split2(v10, v11, hi, lo);
                *(uint32_t*)&g_kh[o1] = hi; *(uint32_t*)&g_kl[o1] = lo;
            } else {
                split2(v00, v01, hi, lo);
                *(uint32_t*)&g_vh[o0] = hi; *(uint32_t*)&g_vl[o0] = lo;
                split2(v10, v11, hi, lo);
                *(uint32_t*)&g_vh[o1] = hi; *(uint32_t*)&g_vl[o1] = lo;
            }
        }
    }
}

// ===========================================================================
// Kernel 2: flash-attention work units on mma.sync bf16 (base-2 softmax).
// Unit = (batch, qtile of 64 rows, kv-chunk of up to 8x64). 3-pass MMA order.
// ===========================================================================
#define ROWB   144
#define QH_OFF 0
#define QL_OFF 9216
#define STG_OFF 18432
#define STG_SZ  36864                       // Kh | Kl | Vh | Vl (9216 each)
#define ATTN_SMEM (STG_OFF + 2 * STG_SZ)    // 92160

__global__ __launch_bounds__(128) void attn_mma_kernel()
{
    extern __shared__ char smem[];
    const uint32_t sb = smem_to_u32(smem);
    const int tid  = threadIdx.x;
    const int w    = tid >> 5;
    const int lane = tid & 31;
    const int b    = blockIdx.y;

    // map blockIdx.x -> (qt, chunk), heavy qtiles first
    int u = blockIdx.x, qt = QT_N - 1, chunk = 0;
    for (;;) {
        int nc = (qt + CHSUB) >> 3;
        if (u < nc) { chunk = u; break; }
        u -= nc; qt--;
    }
    const int nsub = min(CHSUB, (qt + 1) - chunk * CHSUB);
    const int sub0 = chunk * CHSUB;
    const int q0   = qt * 64;

    // ---- stage Q (hi+lo) ----
    {
        const __nv_bfloat16* qhp = g_qh + ((size_t)(b * Tseq + q0)) * Hdim;
        const __nv_bfloat16* qlp = g_ql + ((size_t)(b * Tseq + q0)) * Hdim;
        #pragma unroll
        for (int t = 0; t < 4; t++) {
            int seg = tid + t * 128;
            int r = seg >> 3, o = seg & 7;
            CP_ASYNC16(sb + QH_OFF + r * ROWB + o * 16, qhp + r * 64 + o * 8);
            CP_ASYNC16(sb + QL_OFF + r * ROWB + o * 16, qlp + r * 64 + o * 8);
        }
        CP_COMMIT();
    }

    auto stage = [&](int s, int buf) {
        const uint32_t o = sb + STG_OFF + (uint32_t)buf * STG_SZ;
        const size_t gbase = ((size_t)(b * Tseq + s * 64)) * Hdim;
        #pragma unroll
        for (int t = 0; t < 4; t++) {
            int seg = tid + t * 128;
            int r = seg >> 3, c = seg & 7;
            size_t ge = gbase + r * 64 + c * 8;
            CP_ASYNC16(o + r * ROWB + c * 16,         &g_kh[ge]);
            CP_ASYNC16(o + 9216 + r * ROWB + c * 16,  &g_kl[ge]);
            CP_ASYNC16(o + 18432 + r * ROWB + c * 16, &g_vh[ge]);
            CP_ASYNC16(o + 27648 + r * ROWB + c * 16, &g_vl[ge]);
        }
        CP_COMMIT();
    };

    stage(sub0, 0);
    if (nsub > 1) stage(sub0 + 1, 1);

    const int rsel  = lane & 15;
    const int ksel2 = (lane < 16) ? 0 : 16;
    const int vkv  = ((lane >> 4) & 1) * 8 + (lane & 7);
    const int vh16 = ((lane >> 3) & 1) * 16;

    if (nsub > 1) { CP_WAIT(1); } else { CP_WAIT(0); }
    __syncthreads();

    uint32_t qfh[4][4], qfl[4][4];
    #pragma unroll
    for (int ks = 0; ks < 4; ks++) {
        uint32_t ro = sb + (uint32_t)(w * 16 + rsel) * ROWB + ks * 32 + ksel2;
        LDMATRIX_X4(qfh[ks][0], qfh[ks][1], qfh[ks][2], qfh[ks][3], ro + QH_OFF);
        LDMATRIX_X4(qfl[ks][0], qfl[ks][1], qfl[ks][2], qfl[ks][3], ro + QL_OFF);
    }

    float m0 = -1e30f, m1 = -1e30f, l0 = 0.f, l1 = 0.f;
    float O[8][4];
    #pragma unroll
    for (int f = 0; f < 8; f++)
        #pragma unroll
        for (int r = 0; r < 4; r++) O[f][r] = 0.f;

    const int gr  = lane >> 2;
    const int gc2 = (lane & 3) * 2;

    for (int i = 0; i < nsub; i++) {
        if (i > 0) {
            if (i + 1 < nsub) CP_WAIT(1); else CP_WAIT(0);
            __syncthreads();
        }
        const uint32_t kb = sb + STG_OFF + (uint32_t)(i & 1) * STG_SZ;
        const int sglob = sub0 + i;

        // ---- S = Q K^T (3-way split, 3-pass order) ----
        float S[8][4];
        #pragma unroll
        for (int f = 0; f < 8; f++)
            #pragma unroll
            for (int r = 0; r < 4; r++) S[f][r] = 0.f;

        #pragma unroll
        for (int ks = 0; ks < 4; ks++) {
            uint32_t bh[4][4], bl[4][4];
            #pragma unroll
            for (int nt = 0; nt < 4; nt++) {
                uint32_t ro = kb + (uint32_t)(nt * 16 + rsel) * ROWB + ks * 32 + ksel2;
                LDMATRIX_X4(bh[nt][0], bh[nt][1], bh[nt][2], bh[nt][3], ro);
                LDMATRIX_X4(bl[nt][0], bl[nt][1], bl[nt][2], bl[nt][3], ro + 9216);
            }
            #pragma unroll
            for (int nt = 0; nt < 4; nt++)
                #pragma unroll
                for (int h = 0; h < 2; h++)
                    MMA_BF16(S[nt * 2 + h], qfh[ks], bh[nt][h], bh[nt][h + 2]);
            #pragma unroll
            for (int nt = 0; nt < 4; nt++)
                #pragma unroll
                for (int h = 0; h < 2; h++)
                    MMA_BF16(S[nt * 2 + h], qfh[ks], bl[nt][h], bl[nt][h + 2]);
            #pragma unroll
            for (int nt = 0; nt < 4; nt++)
                #pragma unroll
                for (int h = 0; h < 2; h++)
                    MMA_BF16(S[nt * 2 + h], qfl[ks], bh[nt][h], bh[nt][h + 2]);
        }

        // ---- causal mask (diagonal subtile only) ----
        if (sglob == qt) {
            const int r0 = q0 + w * 16 + gr;
            #pragma unroll
            for (int f = 0; f < 8; f++) {
                const int c = q0 + f * 8 + gc2;
                if (c     > r0)     S[f][0] = -1e30f;
                if (c + 1 > r0)     S[f][1] = -1e30f;
                if (c     > r0 + 8) S[f][2] = -1e30f;
                if (c + 1 > r0 + 8) S[f][3] = -1e30f;
            }
        }

        // ---- online softmax (base 2) ----
        float mx0 = -1e30f, mx1 = -1e30f;
        #pragma unroll
        for (int f = 0; f < 8; f++) {
            mx0 = fmaxf(mx0, fmaxf(S[f][0], S[f][1]));
            mx1 = fmaxf(mx1, fmaxf(S[f][2], S[f][3]));
        }
        mx0 = fmaxf(mx0, __shfl_xor_sync(0xffffffffu, mx0, 1));
        mx0 = fmaxf(mx0, __shfl_xor_sync(0xffffffffu, mx0, 2));
        mx1 = fmaxf(mx1, __shfl_xor_sync(0xffffffffu, mx1, 1));
        mx1 = fmaxf(mx1, __shfl_xor_sync(0xffffffffu, mx1, 2));
        const float mn0 = fmaxf(m0, mx0), mn1 = fmaxf(m1, mx1);
        const float a0 = exp2f(m0 - mn0), a1 = exp2f(m1 - mn1);
        float s0 = 0.f, s1 = 0.f;
        #pragma unroll
        for (int f = 0; f < 8; f++) {
            S[f][0] = exp2f(S[f][0] - mn0);
            S[f][1] = exp2f(S[f][1] - mn0);
            S[f][2] = exp2f(S[f][2] - mn1);
            S[f][3] = exp2f(S[f][3] - mn1);
            s0 += S[f][0] + S[f][1];
            s1 += S[f][2] + S[f][3];
        }
        s0 += __shfl_xor_sync(0xffffffffu, s0, 1);
        s0 += __shfl_xor_sync(0xffffffffu, s0, 2);
        s1 += __shfl_xor_sync(0xffffffffu, s1, 1);
        s1 += __shfl_xor_sync(0xffffffffu, s1, 2);
        l0 = l0 * a0 + s0;
        l1 = l1 * a1 + s1;
        m0 = mn0; m1 = mn1;
        #pragma unroll
        for (int f = 0; f < 8; f++) {
            O[f][0] *= a0; O[f][1] *= a0;
            O[f][2] *= a1; O[f][3] *= a1;
        }

        // ---- O += P V (3-way split, 3-pass order); V via ldmatrix.trans ----
        #pragma unroll
        for (int ks = 0; ks < 4; ks++) {
            uint32_t pha[4], pla[4];
            split2(S[2 * ks][0],     S[2 * ks][1],     pha[0], pla[0]);
            split2(S[2 * ks][2],     S[2 * ks][3],     pha[1], pla[1]);
            split2(S[2 * ks + 1][0], S[2 * ks + 1][1], pha[2], pla[2]);
            split2(S[2 * ks + 1][2], S[2 * ks + 1][3], pha[3], pla[3]);
            uint32_t vh[4][4], vl[4][4];
            #pragma unroll
            for (int ht = 0; ht < 4; ht++) {
                uint32_t ro = kb + 18432u + (uint32_t)(ks * 16 + vkv) * ROWB + ht * 32 + vh16;
                LDMATRIX_X4_TRANS(vh[ht][0], vh[ht][1], vh[ht][2], vh[ht][3], ro);
                LDMATRIX_X4_TRANS(vl[ht][0], vl[ht][1], vl[ht][2], vl[ht][3], ro + 9216);
            }
            #pragma unroll
            for (int ht = 0; ht < 4; ht++)
                #pragma unroll
                for (int h = 0; h < 2; h++)
                    MMA_BF16(O[ht * 2 + h], pha, vh[ht][h], vh[ht][h + 2]);
            #pragma unroll
            for (int ht = 0; ht < 4; ht++)
                #pragma unroll
                for (int h = 0; h < 2; h++)
                    MMA_BF16(O[ht * 2 + h], pha, vl[ht][h], vl[ht][h + 2]);
            #pragma unroll
            for (int ht = 0; ht < 4; ht++)
                #pragma unroll
                for (int h = 0; h < 2; h++)
                    MMA_BF16(O[ht * 2 + h], pla, vh[ht][h], vh[ht][h + 2]);
        }

        __syncthreads();
        if (i + 2 < nsub) stage(sub0 + i + 2, i & 1);
    }

    // ---- epilogue: write partials (m in log2 units) ----
    {
        const size_t base = ((size_t)((b * QT_N + qt) * MAXCH + chunk)) * 4096;
        const int r0 = w * 16 + gr;
        #pragma unroll
        for (int f = 0; f < 8; f++) {
            const int h = f * 8 + gc2;
            *(float2*)&g_pO[base + (size_t)r0 * 64 + h]       = make_float2(O[f][0], O[f][1]);
            *(float2*)&g_pO[base + (size_t)(r0 + 8) * 64 + h] = make_float2(O[f][2], O[f][3]);
        }
        if ((lane & 3) == 0) {
            const size_t sbs = (size_t)((b * QT_N + qt) * MAXCH + chunk) * 64;
            g_pm[sbs + r0]     = m0;  g_pm[sbs + r0 + 8] = m1;
            g_pl[sbs + r0]     = l0;  g_pl[sbs + r0 + 8] = l1;
        }
    }
}

// ===========================================================================
// Kernel 3: combine partials -> final output (predicated prefetch, MLP=4)
// ===========================================================================
__global__ __launch_bounds__(256) void combine_kernel(float* __restrict__ out)
{
    int idx = blockIdx.x * 256 + threadIdx.x;
    int h4  = idx & 15;
    int q   = (Tseq - 1) - ((idx >> 4) & (Tseq - 1));   // heavy q rows first
    int b   = idx >> 15;
    int qt  = q >> 6;
    int row = q & 63;
    int nc  = (qt + CHSUB) >> 3;

    const size_t sbs = (size_t)(b * QT_N + qt) * MAXCH * 64 + row;
    const size_t ob  = (size_t)(b * QT_N + qt) * MAXCH * 4096 + (size_t)row * 64 + h4 * 4;

    float pm[MAXCH], pl[MAXCH];
    float4 p[MAXCH];
    #pragma unroll
    for (int c = 0; c < MAXCH; c++) {
        const bool v = c < nc;
        pm[c] = v ? g_pm[sbs + c * 64] : -1e30f;
        pl[c] = v ? g_pl[sbs + c * 64] : 0.f;
        p[c]  = v ? *(const float4*)&g_pO[ob + (size_t)c * 4096]
                  : make_float4(0.f, 0.f, 0.f, 0.f);
    }

    const float M = fmaxf(fmaxf(pm[0], pm[1]), fmaxf(pm[2], pm[3]));
    float L = 0.f, ox = 0.f, oy = 0.f, oz = 0.f, ow = 0.f;
    #pragma unroll
    for (int c = 0; c < MAXCH; c++) {
        const float wgt = exp2f(pm[c] - M);
        L += pl[c] * wgt;
        ox += wgt * p[c].x; oy += wgt * p[c].y;
        oz += wgt * p[c].z; ow += wgt * p[c].w;
    }
    const float inv = 1.0f / L;
    *(float4*)&out[((size_t)(b * Tseq + q)) * Hdim + h4 * 4] =
        make_float4(ox * inv, oy * inv, oz * inv, ow * inv);
}

// ===========================================================================
extern "C" void kernel_launch(void* const* d_in, const int* in_sizes, int n_in,
                              void* d_out, int out_size)
{
    const float* x  = (const float*)d_in[0];
    const float* wq = (const float*)d_in[1];
    const float* wk = (const float*)d_in[2];
    const float* wv = (const float*)d_in[3];
    float* out = (float*)d_out;

    cudaFuncSetAttribute(proj_mma_kernel, cudaFuncAttributeMaxDynamicSharedMemorySize,
                         PROJ_SMEM);
    cudaFuncSetAttribute(attn_mma_kernel, cudaFuncAttributeMaxDynamicSharedMemorySize,
                         ATTN_SMEM);

    pack_w_kernel<<<(192 * Cdim) / 256, 256>>>(wq, wk, wv);
    proj_mma_kernel<<<BT / 128, 256, PROJ_SMEM>>>(x);
    attn_mma_kernel<<<dim3(80, Bb), 128, ATTN_SMEM>>>();
    combine_kernel<<<(Bb * Tseq * 16) / 256, 256>>>(out);
}

// round 13
// speedup vs baseline: 1.1792x; 1.0871x over previous
#include <cuda_runtime.h>
#include <cuda_bf16.h>
#include <cuda_fp16.h>
#include <cstdint>

// Problem constants
#define Bb    8
#define Tseq  2048
#define Cdim  1024
#define Hdim  64
#define BT    (Bb * Tseq)
#define QSCALE (0.125f * 1.44269504089f)   // H^-0.5 * log2(e): base-2 softmax
#define QT_N  32      // number of 64-row q tiles per batch
#define CHSUB 8       // kv subtiles (of 64) per chunk
#define MAXCH 4       // max chunks per q tile

// Scratch (device globals — no allocation allowed)
__device__ __align__(128) __half g_qh[BT * Hdim];                    // q, scaled, single fp16
__device__ __align__(128) __half g_kh[BT * Hdim], g_kl[BT * Hdim];   // k, 2-term fp16
__device__ __align__(128) __half g_vh[BT * Hdim];                    // v, single fp16
__device__ __align__(128) __nv_bfloat16 g_bh[192 * Cdim], g_bl[192 * Cdim];
// attention partials
__device__ float g_pO[(size_t)Bb * QT_N * MAXCH * 64 * 64];
__device__ float g_pm[Bb * QT_N * MAXCH * 64];
__device__ float g_pl[Bb * QT_N * MAXCH * 64];

// ===========================================================================
// Generic-PTX tensor helpers (sm_80+ ISA)
// ===========================================================================
#define CP_ASYNC16(smem_u32, gptr) \
    asm volatile("cp.async.cg.shared.global [%0], [%1], 16;" \
                 :: "r"(smem_u32), "l"(gptr) : "memory")
#define CP_COMMIT() asm volatile("cp.async.commit_group;" ::: "memory")
#define CP_WAIT(N)  asm volatile("cp.async.wait_group %0;" :: "n"(N) : "memory")

#define LDMATRIX_X4(r0, r1, r2, r3, addr) \
    asm volatile("ldmatrix.sync.aligned.m8n8.x4.shared.b16 {%0,%1,%2,%3}, [%4];" \
                 : "=r"(r0), "=r"(r1), "=r"(r2), "=r"(r3) : "r"(addr))

#define LDMATRIX_X4_TRANS(r0, r1, r2, r3, addr) \
    asm volatile("ldmatrix.sync.aligned.m8n8.x4.trans.shared.b16 {%0,%1,%2,%3}, [%4];" \
                 : "=r"(r0), "=r"(r1), "=r"(r2), "=r"(r3) : "r"(addr))

// non-volatile — pure register ops; data deps order them, ptxas may schedule
#define MMA_BF16(d, a, b0, b1) \
    asm("mma.sync.aligned.m16n8k16.row.col.f32.bf16.bf16.f32 " \
        "{%0,%1,%2,%3}, {%4,%5,%6,%7}, {%8,%9}, {%0,%1,%2,%3};" \
        : "+f"((d)[0]), "+f"((d)[1]), "+f"((d)[2]), "+f"((d)[3]) \
        : "r"((a)[0]), "r"((a)[1]), "r"((a)[2]), "r"((a)[3]), \
          "r"(b0), "r"(b1))

#define MMA_F16(d, a, b0, b1) \
    asm("mma.sync.aligned.m16n8k16.row.col.f32.f16.f16.f32 " \
        "{%0,%1,%2,%3}, {%4,%5,%6,%7}, {%8,%9}, {%0,%1,%2,%3};" \
        : "+f"((d)[0]), "+f"((d)[1]), "+f"((d)[2]), "+f"((d)[3]) \
        : "r"((a)[0]), "r"((a)[1]), "r"((a)[2]), "r"((a)[3]), \
          "r"(b0), "r"(b1))

__device__ __forceinline__ uint32_t smem_to_u32(const void* p) {
    uint32_t a;
    asm("{ .reg .u64 t; cvta.to.shared.u64 t, %1; cvt.u32.u64 %0, t; }" : "=r"(a) : "l"(p));
    return a;
}

// bf16 split (proj A operand)
__device__ __forceinline__ void split2(float x, float y, uint32_t& hi, uint32_t& lo) {
    __nv_bfloat16 hx = __float2bfloat16(x), hy = __float2bfloat16(y);
    __nv_bfloat162 h2 = __halves2bfloat162(hx, hy);
    hi = *(uint32_t*)&h2;
    __nv_bfloat162 l2 = __halves2bfloat162(
        __float2bfloat16(x - __bfloat162float(hx)),
        __float2bfloat16(y - __bfloat162float(hy)));
    lo = *(uint32_t*)&l2;
}

// fp16 split (k storage, P operand)
__device__ __forceinline__ void split2h(float x, float y, uint32_t& hi, uint32_t& lo) {
    __half hx = __float2half(x), hy = __float2half(y);
    __half2 h2 = __halves2half2(hx, hy);
    hi = *(uint32_t*)&h2;
    __half2 l2 = __halves2half2(__float2half(x - __half2float(hx)),
                                __float2half(y - __half2float(hy)));
    lo = *(uint32_t*)&l2;
}

__device__ __forceinline__ uint32_t pack_h2(float x, float y) {
    __half2 h2 = __halves2half2(__float2half(x), __float2half(y));
    return *(uint32_t*)&h2;
}

// ===========================================================================
// Kernel 0: pack + split weights into g_bh/g_bl  [192][1024] K-major (bf16)
// ===========================================================================
__global__ __launch_bounds__(256) void pack_w_kernel(
    const float* __restrict__ wq, const float* __restrict__ wk, const float* __restrict__ wv)
{
    int idx = blockIdx.x * 256 + threadIdx.x;
    int n = idx >> 10;
    int k = idx & 1023;
    const float* w = (n < 64) ? wq : (n < 128) ? wk : wv;
    float v  = w[k * Hdim + (n & 63)];
    __nv_bfloat16 hi = __float2bfloat16(v);
    g_bh[idx] = hi;
    g_bl[idx] = __float2bfloat16(v - __bfloat162float(hi));
}

// ===========================================================================
// Kernel 1: projection GEMM (round-9 bf16 3-pass — empirical optimum).
// Epilogue now emits q (scaled) single fp16, k fp16 hi/lo, v single fp16.
// ===========================================================================
#define ROWB144    144
#define AH_OFF     0                      // 2 x 18432
#define AL_OFF     36864                  // 2 x 18432
#define BH_OFF     73728                  // 2 x 27648
#define BL_OFF     129024                 // 2 x 27648
#define RAW_OFF    184320                 // 32768
#define PROJ_SMEM  217088
#define A_STG      18432
#define B_STG      27648
#define NCHUNK     (Cdim / 64)            // 16

__global__ __launch_bounds__(256, 1) void proj_mma_kernel(const float* __restrict__ x)
{
    extern __shared__ char smem[];
    const uint32_t sb = smem_to_u32(smem);
    const int tid  = threadIdx.x;
    const int wid  = tid >> 5;
    const int lane = tid & 31;
    const int row0 = blockIdx.x * 128;

    const int wm = wid >> 2;
    const int wn = wid & 3;

    float acc[4][6][4];
    #pragma unroll
    for (int i = 0; i < 4; i++)
        #pragma unroll
        for (int j = 0; j < 6; j++)
            #pragma unroll
            for (int r = 0; r < 4; r++) acc[i][j][r] = 0.f;

    auto issue_chunk = [&](int c) {
        const int k0 = c * 64;
        const int s  = c & 1;
        #pragma unroll
        for (int t = 0; t < 8; t++) {
            int seg = tid + t * 256;
            int r = seg >> 4, o = seg & 15;
            CP_ASYNC16(sb + RAW_OFF + r * 256 + o * 16,
                       &x[(size_t)(row0 + r) * Cdim + k0 + o * 4]);
        }
        #pragma unroll
        for (int t = 0; t < 6; t++) {
            int seg = tid + t * 256;
            int r = seg >> 3, o8 = seg & 7;
            size_t ge = (size_t)r * Cdim + k0 + o8 * 8;
            CP_ASYNC16(sb + BH_OFF + s * B_STG + r * ROWB144 + o8 * 16, &g_bh[ge]);
            CP_ASYNC16(sb + BL_OFF + s * B_STG + r * ROWB144 + o8 * 16, &g_bl[ge]);
        }
        CP_COMMIT();
    };

    issue_chunk(0);

    const int rsel = lane & 15;
    const int ksel = (lane < 16) ? 0 : 8;

    for (int c = 0; c < NCHUNK; c++) {
        const int s = c & 1;
        CP_WAIT(0);
        __syncthreads();

        // convert raw fp32 -> Ah/Al stage s  (8 float4 per thread)
        #pragma unroll
        for (int t = 0; t < 8; t++) {
            int seg = tid + t * 256;          // 0..2047
            int r = seg >> 4, kp = seg & 15;
            float4 v = *(const float4*)(smem + RAW_OFF + r * 256 + kp * 16);
            uint32_t h0, l0, h1, l1;
            split2(v.x, v.y, h0, l0);
            split2(v.z, v.w, h1, l1);
            asm volatile("st.shared.v2.b32 [%0], {%1, %2};"
                         :: "r"(sb + AH_OFF + s * A_STG + r * ROWB144 + kp * 8),
                            "r"(h0), "r"(h1) : "memory");
            asm volatile("st.shared.v2.b32 [%0], {%1, %2};"
                         :: "r"(sb + AL_OFF + s * A_STG + r * ROWB144 + kp * 8),
                            "r"(l0), "r"(l1) : "memory");
        }
        __syncthreads();                       // splits visible; raw buffer free

        if (c + 1 < NCHUNK) issue_chunk(c + 1);

        const uint32_t Ah = sb + AH_OFF + s * A_STG;
        const uint32_t Al = sb + AL_OFF + s * A_STG;
        const uint32_t Bh = sb + BH_OFF + s * B_STG;
        const uint32_t Bl = sb + BL_OFF + s * B_STG;

        #pragma unroll
        for (int kk = 0; kk < 4; kk++) {
            const uint32_t kb = (kk * 16 + ksel) * 2;
            uint32_t ah[4][4], al[4][4];
            #pragma unroll
            for (int i = 0; i < 4; i++) {
                uint32_t ro = (uint32_t)(wm * 64 + i * 16 + rsel) * ROWB144 + kb;
                LDMATRIX_X4(ah[i][0], ah[i][1], ah[i][2], ah[i][3], Ah + ro);
                LDMATRIX_X4(al[i][0], al[i][1], al[i][2], al[i][3], Al + ro);
            }
            uint32_t bh[3][4], bl[3][4];
            #pragma unroll
            for (int p = 0; p < 3; p++) {
                uint32_t ro = (uint32_t)(wn * 48 + p * 16 + rsel) * ROWB144 + kb;
                LDMATRIX_X4(bh[p][0], bh[p][1], bh[p][2], bh[p][3], Bh + ro);
                LDMATRIX_X4(bl[p][0], bl[p][1], bl[p][2], bl[p][3], Bl + ro);
            }
            // pass 1: hi * hi  (24 independent MMAs)
            #pragma unroll
            for (int i = 0; i < 4; i++)
                #pragma unroll
                for (int p = 0; p < 3; p++)
                    #pragma unroll
                    for (int h = 0; h < 2; h++)
                        MMA_BF16(acc[i][p * 2 + h], ah[i], bh[p][h], bh[p][h + 2]);
            // pass 2: hi * lo
            #pragma unroll
            for (int i = 0; i < 4; i++)
                #pragma unroll
                for (int p = 0; p < 3; p++)
                    #pragma unroll
                    for (int h = 0; h < 2; h++)
                        MMA_BF16(acc[i][p * 2 + h], ah[i], bl[p][h], bl[p][h + 2]);
            // pass 3: lo * hi
            #pragma unroll
            for (int i = 0; i < 4; i++)
                #pragma unroll
                for (int p = 0; p < 3; p++)
                    #pragma unroll
                    for (int h = 0; h < 2; h++)
                        MMA_BF16(acc[i][p * 2 + h], al[i], bh[p][h], bh[p][h + 2]);
        }
        __syncthreads();
    }

    // Epilogue: q -> scaled single fp16; k -> fp16 hi/lo; v -> single fp16
    #pragma unroll
    for (int i = 0; i < 4; i++) {
        const int rA = row0 + wm * 64 + i * 16 + (lane >> 2);
        #pragma unroll
        for (int j = 0; j < 6; j++) {
            const int col = wn * 48 + j * 8 + (lane & 3) * 2;
            float v00 = acc[i][j][0], v01 = acc[i][j][1];
            float v10 = acc[i][j][2], v11 = acc[i][j][3];
            const int h = col & 63;
            size_t o0 = (size_t)rA * Hdim + h;
            size_t o1 = (size_t)(rA + 8) * Hdim + h;
            if (col < 64) {
                *(uint32_t*)&g_qh[o0] = pack_h2(v00 * QSCALE, v01 * QSCALE);
                *(uint32_t*)&g_qh[o1] = pack_h2(v10 * QSCALE, v11 * QSCALE);
            } else if (col < 128) {
                uint32_t hi, lo;
                split2h(v00, v01, hi, lo);
                *(uint32_t*)&g_kh[o0] = hi; *(uint32_t*)&g_kl[o0] = lo;
                split2h(v10, v11, hi, lo);
                *(uint32_t*)&g_kh[o1] = hi; *(uint32_t*)&g_kl[o1] = lo;
            } else {
                *(uint32_t*)&g_vh[o0] = pack_h2(v00, v01);
                *(uint32_t*)&g_vh[o1] = pack_h2(v10, v11);
            }
        }
    }
}

// ===========================================================================
// Kernel 2: flash-attention on mma.sync fp16 (2-pass splits, base-2 softmax).
// QK: Q single fp16 x K(hi+lo) = 2 passes. PV: P(hi+lo) x V single = 2 passes.
// ===========================================================================
#define ROWB   144
#define QF_OFF 0                            // 9216 (single Q)
#define STG_OFF 9216
#define STG_SZ  27648                       // Kh | Kl | Vh (9216 each)
#define ATTN_SMEM (STG_OFF + 2 * STG_SZ)    // 64512

__global__ __launch_bounds__(128) void attn_mma_kernel()
{
    extern __shared__ char smem[];
    const uint32_t sb = smem_to_u32(smem);
    const int tid  = threadIdx.x;
    const int w    = tid >> 5;
    const int lane = tid & 31;
    const int b    = blockIdx.y;

    // map blockIdx.x -> (qt, chunk), heavy qtiles first
    int u = blockIdx.x, qt = QT_N - 1, chunk = 0;
    for (;;) {
        int nc = (qt + CHSUB) >> 3;
        if (u < nc) { chunk = u; break; }
        u -= nc; qt--;
    }
    const int nsub = min(CHSUB, (qt + 1) - chunk * CHSUB);
    const int sub0 = chunk * CHSUB;
    const int q0   = qt * 64;

    // ---- stage Q (single fp16) ----
    {
        const __half* qp = g_qh + ((size_t)(b * Tseq + q0)) * Hdim;
        #pragma unroll
        for (int t = 0; t < 4; t++) {
            int seg = tid + t * 128;          // 0..511
            int r = seg >> 3, o = seg & 7;
            CP_ASYNC16(sb + QF_OFF + r * ROWB + o * 16, qp + r * 64 + o * 8);
        }
        CP_COMMIT();
    }

    auto stage = [&](int s, int buf) {
        const uint32_t o = sb + STG_OFF + (uint32_t)buf * STG_SZ;
        const size_t gbase = ((size_t)(b * Tseq + s * 64)) * Hdim;
        #pragma unroll
        for (int t = 0; t < 4; t++) {
            int seg = tid + t * 128;
            int r = seg >> 3, c = seg & 7;
            size_t ge = gbase + r * 64 + c * 8;
            CP_ASYNC16(o + r * ROWB + c * 16,         &g_kh[ge]);
            CP_ASYNC16(o + 9216 + r * ROWB + c * 16,  &g_kl[ge]);
            CP_ASYNC16(o + 18432 + r * ROWB + c * 16, &g_vh[ge]);
        }
        CP_COMMIT();
    };

    stage(sub0, 0);
    if (nsub > 1) stage(sub0 + 1, 1);

    const int rsel  = lane & 15;
    const int ksel2 = (lane < 16) ? 0 : 16;
    const int vkv  = ((lane >> 4) & 1) * 8 + (lane & 7);
    const int vh16 = ((lane >> 3) & 1) * 16;

    if (nsub > 1) { CP_WAIT(1); } else { CP_WAIT(0); }
    __syncthreads();

    uint32_t qf[4][4];
    #pragma unroll
    for (int ks = 0; ks < 4; ks++) {
        uint32_t ro = sb + QF_OFF + (uint32_t)(w * 16 + rsel) * ROWB + ks * 32 + ksel2;
        LDMATRIX_X4(qf[ks][0], qf[ks][1], qf[ks][2], qf[ks][3], ro);
    }

    float m0 = -1e30f, m1 = -1e30f, l0 = 0.f, l1 = 0.f;
    float O[8][4];
    #pragma unroll
    for (int f = 0; f < 8; f++)
        #pragma unroll
        for (int r = 0; r < 4; r++) O[f][r] = 0.f;

    const int gr  = lane >> 2;
    const int gc2 = (lane & 3) * 2;

    for (int i = 0; i < nsub; i++) {
        if (i > 0) {
            if (i + 1 < nsub) CP_WAIT(1); else CP_WAIT(0);
            __syncthreads();
        }
        const uint32_t kb = sb + STG_OFF + (uint32_t)(i & 1) * STG_SZ;
        const int sglob = sub0 + i;

        // ---- S = Q K^T (fp16 2-pass: q*kh | q*kl) ----
        float S[8][4];
        #pragma unroll
        for (int f = 0; f < 8; f++)
            #pragma unroll
            for (int r = 0; r < 4; r++) S[f][r] = 0.f;

        #pragma unroll
        for (int ks = 0; ks < 4; ks++) {
            uint32_t bh[4][4], bl[4][4];
            #pragma unroll
            for (int nt = 0; nt < 4; nt++) {
                uint32_t ro = kb + (uint32_t)(nt * 16 + rsel) * ROWB + ks * 32 + ksel2;
                LDMATRIX_X4(bh[nt][0], bh[nt][1], bh[nt][2], bh[nt][3], ro);
                LDMATRIX_X4(bl[nt][0], bl[nt][1], bl[nt][2], bl[nt][3], ro + 9216);
            }
            #pragma unroll
            for (int nt = 0; nt < 4; nt++)
                #pragma unroll
                for (int h = 0; h < 2; h++)
                    MMA_F16(S[nt * 2 + h], qf[ks], bh[nt][h], bh[nt][h + 2]);
            #pragma unroll
            for (int nt = 0; nt < 4; nt++)
                #pragma unroll
                for (int h = 0; h < 2; h++)
                    MMA_F16(S[nt * 2 + h], qf[ks], bl[nt][h], bl[nt][h + 2]);
        }

        // ---- causal mask (diagonal subtile only) ----
        if (sglob == qt) {
            const int r0 = q0 + w * 16 + gr;
            #pragma unroll
            for (int f = 0; f < 8; f++) {
                const int c = q0 + f * 8 + gc2;
                if (c     > r0)     S[f][0] = -1e30f;
                if (c + 1 > r0)     S[f][1] = -1e30f;
                if (c     > r0 + 8) S[f][2] = -1e30f;
                if (c + 1 > r0 + 8) S[f][3] = -1e30f;
            }
        }

        // ---- online softmax (base 2) ----
        float mx0 = -1e30f, mx1 = -1e30f;
        #pragma unroll
        for (int f = 0; f < 8; f++) {
            mx0 = fmaxf(mx0, fmaxf(S[f][0], S[f][1]));
            mx1 = fmaxf(mx1, fmaxf(S[f][2], S[f][3]));
        }
        mx0 = fmaxf(mx0, __shfl_xor_sync(0xffffffffu, mx0, 1));
        mx0 = fmaxf(mx0, __shfl_xor_sync(0xffffffffu, mx0, 2));
        mx1 = fmaxf(mx1, __shfl_xor_sync(0xffffffffu, mx1, 1));
        mx1 = fmaxf(mx1, __shfl_xor_sync(0xffffffffu, mx1, 2));
        const float mn0 = fmaxf(m0, mx0), mn1 = fmaxf(m1, mx1);
        const float a0 = exp2f(m0 - mn0), a1 = exp2f(m1 - mn1);
        float s0 = 0.f, s1 = 0.f;
        #pragma unroll
        for (int f = 0; f < 8; f++) {
            S[f][0] = exp2f(S[f][0] - mn0);
            S[f][1] = exp2f(S[f][1] - mn0);
            S[f][2] = exp2f(S[f][2] - mn1);
            S[f][3] = exp2f(S[f][3] - mn1);
            s0 += S[f][0] + S[f][1];
            s1 += S[f][2] + S[f][3];
        }
        s0 += __shfl_xor_sync(0xffffffffu, s0, 1);
        s0 += __shfl_xor_sync(0xffffffffu, s0, 2);
        s1 += __shfl_xor_sync(0xffffffffu, s1, 1);
        s1 += __shfl_xor_sync(0xffffffffu, s1, 2);
        l0 = l0 * a0 + s0;
        l1 = l1 * a1 + s1;
        m0 = mn0; m1 = mn1;
        #pragma unroll
        for (int f = 0; f < 8; f++) {
            O[f][0] *= a0; O[f][1] *= a0;
            O[f][2] *= a1; O[f][3] *= a1;
        }

        // ---- O += P V (fp16 2-pass: ph*v | pl*v); V via ldmatrix.trans ----
        #pragma unroll
        for (int ks = 0; ks < 4; ks++) {
            uint32_t pha[4], pla[4];
            split2h(S[2 * ks][0],     S[2 * ks][1],     pha[0], pla[0]);
            split2h(S[2 * ks][2],     S[2 * ks][3],     pha[1], pla[1]);
            split2h(S[2 * ks + 1][0], S[2 * ks + 1][1], pha[2], pla[2]);
            split2h(S[2 * ks + 1][2], S[2 * ks + 1][3], pha[3], pla[3]);
            uint32_t vh[4][4];
            #pragma unroll
            for (int ht = 0; ht < 4; ht++) {
                uint32_t ro = kb + 18432u + (uint32_t)(ks * 16 + vkv) * ROWB + ht * 32 + vh16;
                LDMATRIX_X4_TRANS(vh[ht][0], vh[ht][1], vh[ht][2], vh[ht][3], ro);
            }
            #pragma unroll
            for (int ht = 0; ht < 4; ht++)
                #pragma unroll
                for (int h = 0; h < 2; h++)
                    MMA_F16(O[ht * 2 + h], pha, vh[ht][h], vh[ht][h + 2]);
            #pragma unroll
            for (int ht = 0; ht < 4; ht++)
                #pragma unroll
                for (int h = 0; h < 2; h++)
                    MMA_F16(O[ht * 2 + h], pla, vh[ht][h], vh[ht][h + 2]);
        }

        __syncthreads();
        if (i + 2 < nsub) stage(sub0 + i + 2, i & 1);
    }

    // ---- epilogue: write partials (m in log2 units) ----
    {
        const size_t base = ((size_t)((b * QT_N + qt) * MAXCH + chunk)) * 4096;
        const int r0 = w * 16 + gr;
        #pragma unroll
        for (int f = 0; f < 8; f++) {
            const int h = f * 8 + gc2;
            *(float2*)&g_pO[base + (size_t)r0 * 64 + h]       = make_float2(O[f][0], O[f][1]);
            *(float2*)&g_pO[base + (size_t)(r0 + 8) * 64 + h] = make_float2(O[f][2], O[f][3]);
        }
        if ((lane & 3) == 0) {
            const size_t sbs = (size_t)((b * QT_N + qt) * MAXCH + chunk) * 64;
            g_pm[sbs + r0]     = m0;  g_pm[sbs + r0 + 8] = m1;
            g_pl[sbs + r0]     = l0;  g_pl[sbs + r0 + 8] = l1;
        }
    }
}

// ===========================================================================
// Kernel 3: combine partials -> final output (predicated prefetch, MLP=4)
// ===========================================================================
__global__ __launch_bounds__(256) void combine_kernel(float* __restrict__ out)
{
    int idx = blockIdx.x * 256 + threadIdx.x;
    int h4  = idx & 15;
    int q   = (Tseq - 1) - ((idx >> 4) & (Tseq - 1));   // heavy q rows first
    int b   = idx >> 15;
    int qt  = q >> 6;
    int row = q & 63;
    int nc  = (qt + CHSUB) >> 3;

    const size_t sbs = (size_t)(b * QT_N + qt) * MAXCH * 64 + row;
    const size_t ob  = (size_t)(b * QT_N + qt) * MAXCH * 4096 + (size_t)row * 64 + h4 * 4;

    float pm[MAXCH], pl[MAXCH];
    float4 p[MAXCH];
    #pragma unroll
    for (int c = 0; c < MAXCH; c++) {
        const bool v = c < nc;
        pm[c] = v ? g_pm[sbs + c * 64] : -1e30f;
        pl[c] = v ? g_pl[sbs + c * 64] : 0.f;
        p[c]  = v ? *(const float4*)&g_pO[ob + (size_t)c * 4096]
                  : make_float4(0.f, 0.f, 0.f, 0.f);
    }

    const float M = fmaxf(fmaxf(pm[0], pm[1]), fmaxf(pm[2], pm[3]));
    float L = 0.f, ox = 0.f, oy = 0.f, oz = 0.f, ow = 0.f;
    #pragma unroll
    for (int c = 0; c < MAXCH; c++) {
        const float wgt = exp2f(pm[c] - M);
        L += pl[c] * wgt;
        ox += wgt * p[c].x; oy += wgt * p[c].y;
        oz += wgt * p[c].z; ow += wgt * p[c].w;
    }
    const float inv = 1.0f / L;
    *(float4*)&out[((size_t)(b * Tseq + q)) * Hdim + h4 * 4] =
        make_float4(ox * inv, oy * inv, oz * inv, ow * inv);
}

// ===========================================================================
extern "C" void kernel_launch(void* const* d_in, const int* in_sizes, int n_in,
                              void* d_out, int out_size)
{
    const float* x  = (const float*)d_in[0];
    const float* wq = (const float*)d_in[1];
    const float* wk = (const float*)d_in[2];
    const float* wv = (const float*)d_in[3];
    float* out = (float*)d_out;

    cudaFuncSetAttribute(proj_mma_kernel, cudaFuncAttributeMaxDynamicSharedMemorySize,
                         PROJ_SMEM);
    cudaFuncSetAttribute(attn_mma_kernel, cudaFuncAttributeMaxDynamicSharedMemorySize,
                         ATTN_SMEM);

    pack_w_kernel<<<(192 * Cdim) / 256, 256>>>(wq, wk, wv);
    proj_mma_kernel<<<BT / 128, 256, PROJ_SMEM>>>(x);
    attn_mma_kernel<<<dim3(80, Bb), 128, ATTN_SMEM>>>();
    combine_kernel<<<(Bb * Tseq * 16) / 256, 256>>>(out);
}

// round 14
// speedup vs baseline: 1.4687x; 1.2455x over previous
#include <cuda_runtime.h>
#include <cuda_fp16.h>
#include <cstdint>

// Problem constants
#define Bb    8
#define Tseq  2048
#define Cdim  1024
#define Hdim  64
#define BT    (Bb * Tseq)
#define QSCALE (0.125f * 1.44269504089f)   // H^-0.5 * log2(e): base-2 softmax
#define QT_N  32      // number of 64-row q tiles per batch
#define CHSUB 8       // kv subtiles (of 64) per chunk
#define MAXCH 4       // max chunks per q tile

// Scratch (device globals — no allocation allowed)
__device__ __align__(128) __half g_qh[BT * Hdim];                    // q, scaled, single fp16
__device__ __align__(128) __half g_kh[BT * Hdim], g_kl[BT * Hdim];   // k, 2-term fp16
__device__ __align__(128) __half g_vh[BT * Hdim];                    // v, single fp16
__device__ __align__(128) __half g_bw[192 * Cdim];                   // packed weights, fp16
// attention partials
__device__ float g_pO[(size_t)Bb * QT_N * MAXCH * 64 * 64];
__device__ float g_pm[Bb * QT_N * MAXCH * 64];
__device__ float g_pl[Bb * QT_N * MAXCH * 64];

// ===========================================================================
// Generic-PTX tensor helpers (sm_80+ ISA)
// ===========================================================================
#define CP_ASYNC16(smem_u32, gptr) \
    asm volatile("cp.async.cg.shared.global [%0], [%1], 16;" \
                 :: "r"(smem_u32), "l"(gptr) : "memory")
#define CP_COMMIT() asm volatile("cp.async.commit_group;" ::: "memory")
#define CP_WAIT(N)  asm volatile("cp.async.wait_group %0;" :: "n"(N) : "memory")

#define LDMATRIX_X4(r0, r1, r2, r3, addr) \
    asm volatile("ldmatrix.sync.aligned.m8n8.x4.shared.b16 {%0,%1,%2,%3}, [%4];" \
                 : "=r"(r0), "=r"(r1), "=r"(r2), "=r"(r3) : "r"(addr))

#define LDMATRIX_X4_TRANS(r0, r1, r2, r3, addr) \
    asm volatile("ldmatrix.sync.aligned.m8n8.x4.trans.shared.b16 {%0,%1,%2,%3}, [%4];" \
                 : "=r"(r0), "=r"(r1), "=r"(r2), "=r"(r3) : "r"(addr))

// non-volatile — pure register op; data deps order it, ptxas may schedule
#define MMA_F16(d, a, b0, b1) \
    asm("mma.sync.aligned.m16n8k16.row.col.f32.f16.f16.f32 " \
        "{%0,%1,%2,%3}, {%4,%5,%6,%7}, {%8,%9}, {%0,%1,%2,%3};" \
        : "+f"((d)[0]), "+f"((d)[1]), "+f"((d)[2]), "+f"((d)[3]) \
        : "r"((a)[0]), "r"((a)[1]), "r"((a)[2]), "r"((a)[3]), \
          "r"(b0), "r"(b1))

__device__ __forceinline__ uint32_t smem_to_u32(const void* p) {
    uint32_t a;
    asm("{ .reg .u64 t; cvta.to.shared.u64 t, %1; cvt.u32.u64 %0, t; }" : "=r"(a) : "l"(p));
    return a;
}

// fp16 split
__device__ __forceinline__ void split2h(float x, float y, uint32_t& hi, uint32_t& lo) {
    __half hx = __float2half(x), hy = __float2half(y);
    __half2 h2 = __halves2half2(hx, hy);
    hi = *(uint32_t*)&h2;
    __half2 l2 = __halves2half2(__float2half(x - __half2float(hx)),
                                __float2half(y - __half2float(hy)));
    lo = *(uint32_t*)&l2;
}

__device__ __forceinline__ uint32_t pack_h2(float x, float y) {
    __half2 h2 = __halves2half2(__float2half(x), __float2half(y));
    return *(uint32_t*)&h2;
}

// ===========================================================================
// Kernel 0: pack weights into g_bw [192][1024] K-major (single fp16)
// ===========================================================================
__global__ __launch_bounds__(256) void pack_w_kernel(
    const float* __restrict__ wq, const float* __restrict__ wk, const float* __restrict__ wv)
{
    int idx = blockIdx.x * 256 + threadIdx.x;
    int n = idx >> 10;
    int k = idx & 1023;
    const float* w = (n < 64) ? wq : (n < 128) ? wk : wv;
    g_bw[idx] = __float2half(w[k * Hdim + (n & 63)]);
}

// ===========================================================================
// Kernel 1: projection GEMM, fp16 2-pass (x split hi/lo, w single fp16).
// CTA tile 128m x 192n, 256 threads, grid=128. fp32 x cp.async'd raw and
// split to fp16 hi/lo in-kernel.
// ===========================================================================
#define ROWB144    144
#define AH_OFF     0                      // 2 x 18432
#define AL_OFF     36864                  // 2 x 18432
#define BW_OFF     73728                  // 2 x 27648
#define RAW_OFF    129024                 // 32768
#define PROJ_SMEM  161792
#define A_STG      18432
#define B_STG      27648
#define NCHUNK     (Cdim / 64)            // 16

__global__ __launch_bounds__(256, 1) void proj_mma_kernel(const float* __restrict__ x)
{
    extern __shared__ char smem[];
    const uint32_t sb = smem_to_u32(smem);
    const int tid  = threadIdx.x;
    const int wid  = tid >> 5;
    const int lane = tid & 31;
    const int row0 = blockIdx.x * 128;

    const int wm = wid >> 2;
    const int wn = wid & 3;

    float acc[4][6][4];
    #pragma unroll
    for (int i = 0; i < 4; i++)
        #pragma unroll
        for (int j = 0; j < 6; j++)
            #pragma unroll
            for (int r = 0; r < 4; r++) acc[i][j][r] = 0.f;

    auto issue_chunk = [&](int c) {
        const int k0 = c * 64;
        const int s  = c & 1;
        // raw x: 128 rows x 256 B -> 2048 16B segs, 8/thread
        #pragma unroll
        for (int t = 0; t < 8; t++) {
            int seg = tid + t * 256;
            int r = seg >> 4, o = seg & 15;
            CP_ASYNC16(sb + RAW_OFF + r * 256 + o * 16,
                       &x[(size_t)(row0 + r) * Cdim + k0 + o * 4]);
        }
        // B (single fp16): 192 rows x 128 B -> 1536 segs, 6/thread
        #pragma unroll
        for (int t = 0; t < 6; t++) {
            int seg = tid + t * 256;
            int r = seg >> 3, o8 = seg & 7;
            CP_ASYNC16(sb + BW_OFF + s * B_STG + r * ROWB144 + o8 * 16,
                       &g_bw[(size_t)r * Cdim + k0 + o8 * 8]);
        }
        CP_COMMIT();
    };

    issue_chunk(0);

    const int rsel = lane & 15;
    const int ksel = (lane < 16) ? 0 : 8;

    for (int c = 0; c < NCHUNK; c++) {
        const int s = c & 1;
        CP_WAIT(0);
        __syncthreads();

        // convert raw fp32 -> Ah/Al (fp16) stage s  (8 float4 per thread)
        #pragma unroll
        for (int t = 0; t < 8; t++) {
            int seg = tid + t * 256;          // 0..2047
            int r = seg >> 4, kp = seg & 15;
            float4 v = *(const float4*)(smem + RAW_OFF + r * 256 + kp * 16);
            uint32_t h0, l0, h1, l1;
            split2h(v.x, v.y, h0, l0);
            split2h(v.z, v.w, h1, l1);
            asm volatile("st.shared.v2.b32 [%0], {%1, %2};"
                         :: "r"(sb + AH_OFF + s * A_STG + r * ROWB144 + kp * 8),
                            "r"(h0), "r"(h1) : "memory");
            asm volatile("st.shared.v2.b32 [%0], {%1, %2};"
                         :: "r"(sb + AL_OFF + s * A_STG + r * ROWB144 + kp * 8),
                            "r"(l0), "r"(l1) : "memory");
        }
        __syncthreads();                       // splits visible; raw buffer free

        if (c + 1 < NCHUNK) issue_chunk(c + 1);

        const uint32_t Ah = sb + AH_OFF + s * A_STG;
        const uint32_t Al = sb + AL_OFF + s * A_STG;
        const uint32_t Bw = sb + BW_OFF + s * B_STG;

        #pragma unroll
        for (int kk = 0; kk < 4; kk++) {
            const uint32_t kb = (kk * 16 + ksel) * 2;
            uint32_t ah[4][4], al[4][4];
            #pragma unroll
            for (int i = 0; i < 4; i++) {
                uint32_t ro = (uint32_t)(wm * 64 + i * 16 + rsel) * ROWB144 + kb;
                LDMATRIX_X4(ah[i][0], ah[i][1], ah[i][2], ah[i][3], Ah + ro);
                LDMATRIX_X4(al[i][0], al[i][1], al[i][2], al[i][3], Al + ro);
            }
            uint32_t bw[3][4];
            #pragma unroll
            for (int p = 0; p < 3; p++) {
                uint32_t ro = (uint32_t)(wn * 48 + p * 16 + rsel) * ROWB144 + kb;
                LDMATRIX_X4(bw[p][0], bw[p][1], bw[p][2], bw[p][3], Bw + ro);
            }
            // pass 1: xh * w  (24 independent MMAs)
            #pragma unroll
            for (int i = 0; i < 4; i++)
                #pragma unroll
                for (int p = 0; p < 3; p++)
                    #pragma unroll
                    for (int h = 0; h < 2; h++)
                        MMA_F16(acc[i][p * 2 + h], ah[i], bw[p][h], bw[p][h + 2]);
            // pass 2: xl * w
            #pragma unroll
            for (int i = 0; i < 4; i++)
                #pragma unroll
                for (int p = 0; p < 3; p++)
                    #pragma unroll
                    for (int h = 0; h < 2; h++)
                        MMA_F16(acc[i][p * 2 + h], al[i], bw[p][h], bw[p][h + 2]);
        }
        __syncthreads();
    }

    // Epilogue: q -> scaled single fp16; k -> fp16 hi/lo; v -> single fp16
    #pragma unroll
    for (int i = 0; i < 4; i++) {
        const int rA = row0 + wm * 64 + i * 16 + (lane >> 2);
        #pragma unroll
        for (int j = 0; j < 6; j++) {
            const int col = wn * 48 + j * 8 + (lane & 3) * 2;
            float v00 = acc[i][j][0], v01 = acc[i][j][1];
            float v10 = acc[i][j][2], v11 = acc[i][j][3];
            const int h = col & 63;
            size_t o0 = (size_t)rA * Hdim + h;
            size_t o1 = (size_t)(rA + 8) * Hdim + h;
            if (col < 64) {
                *(uint32_t*)&g_qh[o0] = pack_h2(v00 * QSCALE, v01 * QSCALE);
                *(uint32_t*)&g_qh[o1] = pack_h2(v10 * QSCALE, v11 * QSCALE);
            } else if (col < 128) {
                uint32_t hi, lo;
                split2h(v00, v01, hi, lo);
                *(uint32_t*)&g_kh[o0] = hi; *(uint32_t*)&g_kl[o0] = lo;
                split2h(v10, v11, hi, lo);
                *(uint32_t*)&g_kh[o1] = hi; *(uint32_t*)&g_kl[o1] = lo;
            } else {
                *(uint32_t*)&g_vh[o0] = pack_h2(v00, v01);
                *(uint32_t*)&g_vh[o1] = pack_h2(v10, v11);
            }
        }
    }
}

// ===========================================================================
// Kernel 2: flash-attention on mma.sync fp16 (2-pass splits, base-2 softmax).
// QK: Q single fp16 x K(hi+lo) = 2 passes. PV: P(hi+lo) x V single = 2 passes.
// ===========================================================================
#define ROWB   144
#define QF_OFF 0                            // 9216 (single Q)
#define STG_OFF 9216
#define STG_SZ  27648                       // Kh | Kl | Vh (9216 each)
#define ATTN_SMEM (STG_OFF + 2 * STG_SZ)    // 64512

__global__ __launch_bounds__(128) void attn_mma_kernel()
{
    extern __shared__ char smem[];
    const uint32_t sb = smem_to_u32(smem);
    const int tid  = threadIdx.x;
    const int w    = tid >> 5;
    const int lane = tid & 31;
    const int b    = blockIdx.y;

    // map blockIdx.x -> (qt, chunk), heavy qtiles first
    int u = blockIdx.x, qt = QT_N - 1, chunk = 0;
    for (;;) {
        int nc = (qt + CHSUB) >> 3;
        if (u < nc) { chunk = u; break; }
        u -= nc; qt--;
    }
    const int nsub = min(CHSUB, (qt + 1) - chunk * CHSUB);
    const int sub0 = chunk * CHSUB;
    const int q0   = qt * 64;

    // ---- stage Q (single fp16) ----
    {
        const __half* qp = g_qh + ((size_t)(b * Tseq + q0)) * Hdim;
        #pragma unroll
        for (int t = 0; t < 4; t++) {
            int seg = tid + t * 128;          // 0..511
            int r = seg >> 3, o = seg & 7;
            CP_ASYNC16(sb + QF_OFF + r * ROWB + o * 16, qp + r * 64 + o * 8);
        }
        CP_COMMIT();
    }

    auto stage = [&](int s, int buf) {
        const uint32_t o = sb + STG_OFF + (uint32_t)buf * STG_SZ;
        const size_t gbase = ((size_t)(b * Tseq + s * 64)) * Hdim;
        #pragma unroll
        for (int t = 0; t < 4; t++) {
            int seg = tid + t * 128;
            int r = seg >> 3, c = seg & 7;
            size_t ge = gbase + r * 64 + c * 8;
            CP_ASYNC16(o + r * ROWB + c * 16,         &g_kh[ge]);
            CP_ASYNC16(o + 9216 + r * ROWB + c * 16,  &g_kl[ge]);
            CP_ASYNC16(o + 18432 + r * ROWB + c * 16, &g_vh[ge]);
        }
        CP_COMMIT();
    };

    stage(sub0, 0);
    if (nsub > 1) stage(sub0 + 1, 1);

    const int rsel  = lane & 15;
    const int ksel2 = (lane < 16) ? 0 : 16;
    const int vkv  = ((lane >> 4) & 1) * 8 + (lane & 7);
    const int vh16 = ((lane >> 3) & 1) * 16;

    if (nsub > 1) { CP_WAIT(1); } else { CP_WAIT(0); }
    __syncthreads();

    uint32_t qf[4][4];
    #pragma unroll
    for (int ks = 0; ks < 4; ks++) {
        uint32_t ro = sb + QF_OFF + (uint32_t)(w * 16 + rsel) * ROWB + ks * 32 + ksel2;
        LDMATRIX_X4(qf[ks][0], qf[ks][1], qf[ks][2], qf[ks][3], ro);
    }

    float m0 = -1e30f, m1 = -1e30f, l0 = 0.f, l1 = 0.f;
    float O[8][4];
    #pragma unroll
    for (int f = 0; f < 8; f++)
        #pragma unroll
        for (int r = 0; r < 4; r++) O[f][r] = 0.f;

    const int gr  = lane >> 2;
    const int gc2 = (lane & 3) * 2;

    for (int i = 0; i < nsub; i++) {
        if (i > 0) {
            if (i + 1 < nsub) CP_WAIT(1); else CP_WAIT(0);
            __syncthreads();
        }
        const uint32_t kb = sb + STG_OFF + (uint32_t)(i & 1) * STG_SZ;
        const int sglob = sub0 + i;

        // ---- S = Q K^T (fp16 2-pass: q*kh | q*kl) ----
        float S[8][4];
        #pragma unroll
        for (int f = 0; f < 8; f++)
            #pragma unroll
            for (int r = 0; r < 4; r++) S[f][r] = 0.f;

        #pragma unroll
        for (int ks = 0; ks < 4; ks++) {
            uint32_t bh[4][4], bl[4][4];
            #pragma unroll
            for (int nt = 0; nt < 4; nt++) {
                uint32_t ro = kb + (uint32_t)(nt * 16 + rsel) * ROWB + ks * 32 + ksel2;
                LDMATRIX_X4(bh[nt][0], bh[nt][1], bh[nt][2], bh[nt][3], ro);
                LDMATRIX_X4(bl[nt][0], bl[nt][1], bl[nt][2], bl[nt][3], ro + 9216);
            }
            #pragma unroll
            for (int nt = 0; nt < 4; nt++)
                #pragma unroll
                for (int h = 0; h < 2; h++)
                    MMA_F16(S[nt * 2 + h], qf[ks], bh[nt][h], bh[nt][h + 2]);
            #pragma unroll
            for (int nt = 0; nt < 4; nt++)
                #pragma unroll
                for (int h = 0; h < 2; h++)
                    MMA_F16(S[nt * 2 + h], qf[ks], bl[nt][h], bl[nt][h + 2]);
        }

        // ---- causal mask (diagonal subtile only) ----
        if (sglob == qt) {
            const int r0 = q0 + w * 16 + gr;
            #pragma unroll
            for (int f = 0; f < 8; f++) {
                const int c = q0 + f * 8 + gc2;
                if (c     > r0)     S[f][0] = -1e30f;
                if (c + 1 > r0)     S[f][1] = -1e30f;
                if (c     > r0 + 8) S[f][2] = -1e30f;
                if (c + 1 > r0 + 8) S[f][3] = -1e30f;
            }
        }

        // ---- online softmax (base 2) ----
        float mx0 = -1e30f, mx1 = -1e30f;
        #pragma unroll
        for (int f = 0; f < 8; f++) {
            mx0 = fmaxf(mx0, fmaxf(S[f][0], S[f][1]));
            mx1 = fmaxf(mx1, fmaxf(S[f][2], S[f][3]));
        }
        mx0 = fmaxf(mx0, __shfl_xor_sync(0xffffffffu, mx0, 1));
        mx0 = fmaxf(mx0, __shfl_xor_sync(0xffffffffu, mx0, 2));
        mx1 = fmaxf(mx1, __shfl_xor_sync(0xffffffffu, mx1, 1));
        mx1 = fmaxf(mx1, __shfl_xor_sync(0xffffffffu, mx1, 2));
        const float mn0 = fmaxf(m0, mx0), mn1 = fmaxf(m1, mx1);
        const float a0 = exp2f(m0 - mn0), a1 = exp2f(m1 - mn1);
        float s0 = 0.f, s1 = 0.f;
        #pragma unroll
        for (int f = 0; f < 8; f++) {
            S[f][0] = exp2f(S[f][0] - mn0);
            S[f][1] = exp2f(S[f][1] - mn0);
            S[f][2] = exp2f(S[f][2] - mn1);
            S[f][3] = exp2f(S[f][3] - mn1);
            s0 += S[f][0] + S[f][1];
            s1 += S[f][2] + S[f][3];
        }
        s0 += __shfl_xor_sync(0xffffffffu, s0, 1);
        s0 += __shfl_xor_sync(0xffffffffu, s0, 2);
        s1 += __shfl_xor_sync(0xffffffffu, s1, 1);
        s1 += __shfl_xor_sync(0xffffffffu, s1, 2);
        l0 = l0 * a0 + s0;
        l1 = l1 * a1 + s1;
        m0 = mn0; m1 = mn1;
        #pragma unroll
        for (int f = 0; f < 8; f++) {
            O[f][0] *= a0; O[f][1] *= a0;
            O[f][2] *= a1; O[f][3] *= a1;
        }

        // ---- O += P V (fp16 2-pass: ph*v | pl*v); V via ldmatrix.trans ----
        #pragma unroll
        for (int ks = 0; ks < 4; ks++) {
            uint32_t pha[4], pla[4];
            split2h(S[2 * ks][0],     S[2 * ks][1],     pha[0], pla[0]);
            split2h(S[2 * ks][2],     S[2 * ks][3],     pha[1], pla[1]);
            split2h(S[2 * ks + 1][0], S[2 * ks + 1][1], pha[2], pla[2]);
            split2h(S[2 * ks + 1][2], S[2 * ks + 1][3], pha[3], pla[3]);
            uint32_t vh[4][4];
            #pragma unroll
            for (int ht = 0; ht < 4; ht++) {
                uint32_t ro = kb + 18432u + (uint32_t)(ks * 16 + vkv) * ROWB + ht * 32 + vh16;
                LDMATRIX_X4_TRANS(vh[ht][0], vh[ht][1], vh[ht][2], vh[ht][3], ro);
            }
            #pragma unroll
            for (int ht = 0; ht < 4; ht++)
                #pragma unroll
                for (int h = 0; h < 2; h++)
                    MMA_F16(O[ht * 2 + h], pha, vh[ht][h], vh[ht][h + 2]);
            #pragma unroll
            for (int ht = 0; ht < 4; ht++)
                #pragma unroll
                for (int h = 0; h < 2; h++)
                    MMA_F16(O[ht * 2 + h], pla, vh[ht][h], vh[ht][h + 2]);
        }

        __syncthreads();
        if (i + 2 < nsub) stage(sub0 + i + 2, i & 1);
    }

    // ---- epilogue: write partials (m in log2 units) ----
    {
        const size_t base = ((size_t)((b * QT_N + qt) * MAXCH + chunk)) * 4096;
        const int r0 = w * 16 + gr;
        #pragma unroll
        for (int f = 0; f < 8; f++) {
            const int h = f * 8 + gc2;
            *(float2*)&g_pO[base + (size_t)r0 * 64 + h]       = make_float2(O[f][0], O[f][1]);
            *(float2*)&g_pO[base + (size_t)(r0 + 8) * 64 + h] = make_float2(O[f][2], O[f][3]);
        }
        if ((lane & 3) == 0) {
            const size_t sbs = (size_t)((b * QT_N + qt) * MAXCH + chunk) * 64;
            g_pm[sbs + r0]     = m0;  g_pm[sbs + r0 + 8] = m1;
            g_pl[sbs + r0]     = l0;  g_pl[sbs + r0 + 8] = l1;
        }
    }
}

// ===========================================================================
// Kernel 3: combine partials -> final output (predicated prefetch, MLP=4)
// ===========================================================================
__global__ __launch_bounds__(256) void combine_kernel(float* __restrict__ out)
{
    int idx = blockIdx.x * 256 + threadIdx.x;
    int h4  = idx & 15;
    int q   = (Tseq - 1) - ((idx >> 4) & (Tseq - 1));   // heavy q rows first
    int b   = idx >> 15;
    int qt  = q >> 6;
    int row = q & 63;
    int nc  = (qt + CHSUB) >> 3;

    const size_t sbs = (size_t)(b * QT_N + qt) * MAXCH * 64 + row;
    const size_t ob  = (size_t)(b * QT_N + qt) * MAXCH * 4096 + (size_t)row * 64 + h4 * 4;

    float pm[MAXCH], pl[MAXCH];
    float4 p[MAXCH];
    #pragma unroll
    for (int c = 0; c < MAXCH; c++) {
        const bool v = c < nc;
        pm[c] = v ? g_pm[sbs + c * 64] : -1e30f;
        pl[c] = v ? g_pl[sbs + c * 64] : 0.f;
        p[c]  = v ? *(const float4*)&g_pO[ob + (size_t)c * 4096]
                  : make_float4(0.f, 0.f, 0.f, 0.f);
    }

    const float M = fmaxf(fmaxf(pm[0], pm[1]), fmaxf(pm[2], pm[3]));
    float L = 0.f, ox = 0.f, oy = 0.f, oz = 0.f, ow = 0.f;
    #pragma unroll
    for (int c = 0; c < MAXCH; c++) {
        const float wgt = exp2f(pm[c] - M);
        L += pl[c] * wgt;
        ox += wgt * p[c].x; oy += wgt * p[c].y;
        oz += wgt * p[c].z; ow += wgt * p[c].w;
    }
    const float inv = 1.0f / L;
    *(float4*)&out[((size_t)(b * Tseq + q)) * Hdim + h4 * 4] =
        make_float4(ox * inv, oy * inv, oz * inv, ow * inv);
}

// ===========================================================================
extern "C" void kernel_launch(void* const* d_in, const int* in_sizes, int n_in,
                              void* d_out, int out_size)
{
    const float* x  = (const float*)d_in[0];
    const float* wq = (const float*)d_in[1];
    const float* wk = (const float*)d_in[2];
    const float* wv = (const float*)d_in[3];
    float* out = (float*)d_out;

    cudaFuncSetAttribute(proj_mma_kernel, cudaFuncAttributeMaxDynamicSharedMemorySize,
                         PROJ_SMEM);
    cudaFuncSetAttribute(attn_mma_kernel, cudaFuncAttributeMaxDynamicSharedMemorySize,
                         ATTN_SMEM);

    pack_w_kernel<<<(192 * Cdim) / 256, 256>>>(wq, wk, wv);
    proj_mma_kernel<<<BT / 128, 256, PROJ_SMEM>>>(x);
    attn_mma_kernel<<<dim3(80, Bb), 128, ATTN_SMEM>>>();
    combine_kernel<<<(Bb * Tseq * 16) / 256, 256>>>(out);
}

// round 15
// speedup vs baseline: 1.8590x; 1.2657x over previous
#include <cuda_runtime.h>
#include <cuda_fp16.h>
#include <cstdint>

// Problem constants
#define Bb    8
#define Tseq  2048
#define Cdim  1024
#define Hdim  64
#define BT    (Bb * Tseq)
#define QSCALE (0.125f * 1.44269504089f)   // H^-0.5 * log2(e): base-2 softmax
#define QT_N  32      // number of 64-row q tiles per batch
#define CHSUB 8       // kv subtiles (of 64) per chunk
#define MAXCH 4       // max chunks per q tile

// Scratch (device globals — no allocation allowed)
__device__ __align__(128) __half g_qh[BT * Hdim];    // q, scaled, fp16
__device__ __align__(128) __half g_kh[BT * Hdim];    // k, fp16
__device__ __align__(128) __half g_vh[BT * Hdim];    // v, fp16
__device__ __align__(128) __half g_bw[192 * Cdim];   // packed weights, fp16
// attention partials
__device__ float g_pO[(size_t)Bb * QT_N * MAXCH * 64 * 64];
__device__ float g_pm[Bb * QT_N * MAXCH * 64];
__device__ float g_pl[Bb * QT_N * MAXCH * 64];

// ===========================================================================
// Generic-PTX tensor helpers (sm_80+ ISA)
// ===========================================================================
#define CP_ASYNC16(smem_u32, gptr) \
    asm volatile("cp.async.cg.shared.global [%0], [%1], 16;" \
                 :: "r"(smem_u32), "l"(gptr) : "memory")
#define CP_COMMIT() asm volatile("cp.async.commit_group;" ::: "memory")
#define CP_WAIT(N)  asm volatile("cp.async.wait_group %0;" :: "n"(N) : "memory")

#define LDMATRIX_X4(r0, r1, r2, r3, addr) \
    asm volatile("ldmatrix.sync.aligned.m8n8.x4.shared.b16 {%0,%1,%2,%3}, [%4];" \
                 : "=r"(r0), "=r"(r1), "=r"(r2), "=r"(r3) : "r"(addr))

#define LDMATRIX_X4_TRANS(r0, r1, r2, r3, addr) \
    asm volatile("ldmatrix.sync.aligned.m8n8.x4.trans.shared.b16 {%0,%1,%2,%3}, [%4];" \
                 : "=r"(r0), "=r"(r1), "=r"(r2), "=r"(r3) : "r"(addr))

// non-volatile — pure register op; data deps order it, ptxas may schedule
#define MMA_F16(d, a, b0, b1) \
    asm("mma.sync.aligned.m16n8k16.row.col.f32.f16.f16.f32 " \
        "{%0,%1,%2,%3}, {%4,%5,%6,%7}, {%8,%9}, {%0,%1,%2,%3};" \
        : "+f"((d)[0]), "+f"((d)[1]), "+f"((d)[2]), "+f"((d)[3]) \
        : "r"((a)[0]), "r"((a)[1]), "r"((a)[2]), "r"((a)[3]), \
          "r"(b0), "r"(b1))

__device__ __forceinline__ uint32_t smem_to_u32(const void* p) {
    uint32_t a;
    asm("{ .reg .u64 t; cvta.to.shared.u64 t, %1; cvt.u32.u64 %0, t; }" : "=r"(a) : "l"(p));
    return a;
}

// fp16 split (proj x operand)
__device__ __forceinline__ void split2h(float x, float y, uint32_t& hi, uint32_t& lo) {
    __half hx = __float2half(x), hy = __float2half(y);
    __half2 h2 = __halves2half2(hx, hy);
    hi = *(uint32_t*)&h2;
    __half2 l2 = __halves2half2(__float2half(x - __half2float(hx)),
                                __float2half(y - __half2float(hy)));
    lo = *(uint32_t*)&l2;
}

__device__ __forceinline__ uint32_t pack_h2(float x, float y) {
    __half2 h2 = __halves2half2(__float2half(x), __float2half(y));
    return *(uint32_t*)&h2;
}

// ===========================================================================
// Kernel 0: pack weights into g_bw [192][1024] K-major (single fp16)
// ===========================================================================
__global__ __launch_bounds__(256) void pack_w_kernel(
    const float* __restrict__ wq, const float* __restrict__ wk, const float* __restrict__ wv)
{
    int idx = blockIdx.x * 256 + threadIdx.x;
    int n = idx >> 10;
    int k = idx & 1023;
    const float* w = (n < 64) ? wq : (n < 128) ? wk : wv;
    g_bw[idx] = __float2half(w[k * Hdim + (n & 63)]);
}

// ===========================================================================
// Kernel 1: projection GEMM, fp16 2-pass (x split hi/lo, w single fp16).
// CTA tile 128m x 192n, 256 threads, grid=128.
// ===========================================================================
#define ROWB144    144
#define AH_OFF     0                      // 2 x 18432
#define AL_OFF     36864                  // 2 x 18432
#define BW_OFF     73728                  // 2 x 27648
#define RAW_OFF    129024                 // 32768
#define PROJ_SMEM  161792
#define A_STG      18432
#define B_STG      27648
#define NCHUNK     (Cdim / 64)            // 16

__global__ __launch_bounds__(256, 1) void proj_mma_kernel(const float* __restrict__ x)
{
    extern __shared__ char smem[];
    const uint32_t sb = smem_to_u32(smem);
    const int tid  = threadIdx.x;
    const int wid  = tid >> 5;
    const int lane = tid & 31;
    const int row0 = blockIdx.x * 128;

    const int wm = wid >> 2;
    const int wn = wid & 3;

    float acc[4][6][4];
    #pragma unroll
    for (int i = 0; i < 4; i++)
        #pragma unroll
        for (int j = 0; j < 6; j++)
            #pragma unroll
            for (int r = 0; r < 4; r++) acc[i][j][r] = 0.f;

    auto issue_chunk = [&](int c) {
        const int k0 = c * 64;
        const int s  = c & 1;
        #pragma unroll
        for (int t = 0; t < 8; t++) {
            int seg = tid + t * 256;
            int r = seg >> 4, o = seg & 15;
            CP_ASYNC16(sb + RAW_OFF + r * 256 + o * 16,
                       &x[(size_t)(row0 + r) * Cdim + k0 + o * 4]);
        }
        #pragma unroll
        for (int t = 0; t < 6; t++) {
            int seg = tid + t * 256;
            int r = seg >> 3, o8 = seg & 7;
            CP_ASYNC16(sb + BW_OFF + s * B_STG + r * ROWB144 + o8 * 16,
                       &g_bw[(size_t)r * Cdim + k0 + o8 * 8]);
        }
        CP_COMMIT();
    };

    issue_chunk(0);

    const int rsel = lane & 15;
    const int ksel = (lane < 16) ? 0 : 8;

    for (int c = 0; c < NCHUNK; c++) {
        const int s = c & 1;
        CP_WAIT(0);
        __syncthreads();

        // convert raw fp32 -> Ah/Al (fp16) stage s  (8 float4 per thread)
        #pragma unroll
        for (int t = 0; t < 8; t++) {
            int seg = tid + t * 256;          // 0..2047
            int r = seg >> 4, kp = seg & 15;
            float4 v = *(const float4*)(smem + RAW_OFF + r * 256 + kp * 16);
            uint32_t h0, l0, h1, l1;
            split2h(v.x, v.y, h0, l0);
            split2h(v.z, v.w, h1, l1);
            asm volatile("st.shared.v2.b32 [%0], {%1, %2};"
                         :: "r"(sb + AH_OFF + s * A_STG + r * ROWB144 + kp * 8),
                            "r"(h0), "r"(h1) : "memory");
            asm volatile("st.shared.v2.b32 [%0], {%1, %2};"
                         :: "r"(sb + AL_OFF + s * A_STG + r * ROWB144 + kp * 8),
                            "r"(l0), "r"(l1) : "memory");
        }
        __syncthreads();                       // splits visible; raw buffer free

        if (c + 1 < NCHUNK) issue_chunk(c + 1);

        const uint32_t Ah = sb + AH_OFF + s * A_STG;
        const uint32_t Al = sb + AL_OFF + s * A_STG;
        const uint32_t Bw = sb + BW_OFF + s * B_STG;

        #pragma unroll
        for (int kk = 0; kk < 4; kk++) {
            const uint32_t kb = (kk * 16 + ksel) * 2;
            uint32_t ah[4][4], al[4][4];
            #pragma unroll
            for (int i = 0; i < 4; i++) {
                uint32_t ro = (uint32_t)(wm * 64 + i * 16 + rsel) * ROWB144 + kb;
                LDMATRIX_X4(ah[i][0], ah[i][1], ah[i][2], ah[i][3], Ah + ro);
                LDMATRIX_X4(al[i][0], al[i][1], al[i][2], al[i][3], Al + ro);
            }
            uint32_t bw[3][4];
            #pragma unroll
            for (int p = 0; p < 3; p++) {
                uint32_t ro = (uint32_t)(wn * 48 + p * 16 + rsel) * ROWB144 + kb;
                LDMATRIX_X4(bw[p][0], bw[p][1], bw[p][2], bw[p][3], Bw + ro);
            }
            // pass 1: xh * w  (24 independent MMAs)
            #pragma unroll
            for (int i = 0; i < 4; i++)
                #pragma unroll
                for (int p = 0; p < 3; p++)
                    #pragma unroll
                    for (int h = 0; h < 2; h++)
                        MMA_F16(acc[i][p * 2 + h], ah[i], bw[p][h], bw[p][h + 2]);
            // pass 2: xl * w
            #pragma unroll
            for (int i = 0; i < 4; i++)
                #pragma unroll
                for (int p = 0; p < 3; p++)
                    #pragma unroll
                    for (int h = 0; h < 2; h++)
                        MMA_F16(acc[i][p * 2 + h], al[i], bw[p][h], bw[p][h + 2]);
        }
        __syncthreads();
    }

    // Epilogue: q -> scaled fp16; k -> fp16; v -> fp16 (all single)
    #pragma unroll
    for (int i = 0; i < 4; i++) {
        const int rA = row0 + wm * 64 + i * 16 + (lane >> 2);
        #pragma unroll
        for (int j = 0; j < 6; j++) {
            const int col = wn * 48 + j * 8 + (lane & 3) * 2;
            float v00 = acc[i][j][0], v01 = acc[i][j][1];
            float v10 = acc[i][j][2], v11 = acc[i][j][3];
            const int h = col & 63;
            size_t o0 = (size_t)rA * Hdim + h;
            size_t o1 = (size_t)(rA + 8) * Hdim + h;
            if (col < 64) {
                *(uint32_t*)&g_qh[o0] = pack_h2(v00 * QSCALE, v01 * QSCALE);
                *(uint32_t*)&g_qh[o1] = pack_h2(v10 * QSCALE, v11 * QSCALE);
            } else if (col < 128) {
                *(uint32_t*)&g_kh[o0] = pack_h2(v00, v01);
                *(uint32_t*)&g_kh[o1] = pack_h2(v10, v11);
            } else {
                *(uint32_t*)&g_vh[o0] = pack_h2(v00, v01);
                *(uint32_t*)&g_vh[o1] = pack_h2(v10, v11);
            }
        }
    }
}

// ===========================================================================
// Kernel 2: flash-attention on mma.sync fp16, single-precision operands
// (1 pass per GEMM), base-2 softmax.
// ===========================================================================
#define ROWB   144
#define QF_OFF 0                            // 9216 (single Q)
#define STG_OFF 9216
#define STG_SZ  18432                       // Kh | Vh (9216 each)
#define ATTN_SMEM (STG_OFF + 2 * STG_SZ)    // 46080

__global__ __launch_bounds__(128) void attn_mma_kernel()
{
    extern __shared__ char smem[];
    const uint32_t sb = smem_to_u32(smem);
    const int tid  = threadIdx.x;
    const int w    = tid >> 5;
    const int lane = tid & 31;
    const int b    = blockIdx.y;

    // map blockIdx.x -> (qt, chunk), heavy qtiles first
    int u = blockIdx.x, qt = QT_N - 1, chunk = 0;
    for (;;) {
        int nc = (qt + CHSUB) >> 3;
        if (u < nc) { chunk = u; break; }
        u -= nc; qt--;
    }
    const int nsub = min(CHSUB, (qt + 1) - chunk * CHSUB);
    const int sub0 = chunk * CHSUB;
    const int q0   = qt * 64;

    // ---- stage Q (single fp16) ----
    {
        const __half* qp = g_qh + ((size_t)(b * Tseq + q0)) * Hdim;
        #pragma unroll
        for (int t = 0; t < 4; t++) {
            int seg = tid + t * 128;          // 0..511
            int r = seg >> 3, o = seg & 7;
            CP_ASYNC16(sb + QF_OFF + r * ROWB + o * 16, qp + r * 64 + o * 8);
        }
        CP_COMMIT();
    }

    auto stage = [&](int s, int buf) {
        const uint32_t o = sb + STG_OFF + (uint32_t)buf * STG_SZ;
        const size_t gbase = ((size_t)(b * Tseq + s * 64)) * Hdim;
        #pragma unroll
        for (int t = 0; t < 4; t++) {
            int seg = tid + t * 128;
            int r = seg >> 3, c = seg & 7;
            size_t ge = gbase + r * 64 + c * 8;
            CP_ASYNC16(o + r * ROWB + c * 16,        &g_kh[ge]);
            CP_ASYNC16(o + 9216 + r * ROWB + c * 16, &g_vh[ge]);
        }
        CP_COMMIT();
    };

    stage(sub0, 0);
    if (nsub > 1) stage(sub0 + 1, 1);

    const int rsel  = lane & 15;
    const int ksel2 = (lane < 16) ? 0 : 16;
    const int vkv  = ((lane >> 4) & 1) * 8 + (lane & 7);
    const int vh16 = ((lane >> 3) & 1) * 16;

    if (nsub > 1) { CP_WAIT(1); } else { CP_WAIT(0); }
    __syncthreads();

    uint32_t qf[4][4];
    #pragma unroll
    for (int ks = 0; ks < 4; ks++) {
        uint32_t ro = sb + QF_OFF + (uint32_t)(w * 16 + rsel) * ROWB + ks * 32 + ksel2;
        LDMATRIX_X4(qf[ks][0], qf[ks][1], qf[ks][2], qf[ks][3], ro);
    }

    float m0 = -1e30f, m1 = -1e30f, l0 = 0.f, l1 = 0.f;
    float O[8][4];
    #pragma unroll
    for (int f = 0; f < 8; f++)
        #pragma unroll
        for (int r = 0; r < 4; r++) O[f][r] = 0.f;

    const int gr  = lane >> 2;
    const int gc2 = (lane & 3) * 2;

    for (int i = 0; i < nsub; i++) {
        if (i > 0) {
            if (i + 1 < nsub) CP_WAIT(1); else CP_WAIT(0);
            __syncthreads();
        }
        const uint32_t kb = sb + STG_OFF + (uint32_t)(i & 1) * STG_SZ;
        const int sglob = sub0 + i;

        // ---- S = Q K^T (fp16 single, 1 pass) ----
        float S[8][4];
        #pragma unroll
        for (int f = 0; f < 8; f++)
            #pragma unroll
            for (int r = 0; r < 4; r++) S[f][r] = 0.f;

        #pragma unroll
        for (int ks = 0; ks < 4; ks++) {
            uint32_t bh[4][4];
            #pragma unroll
            for (int nt = 0; nt < 4; nt++) {
                uint32_t ro = kb + (uint32_t)(nt * 16 + rsel) * ROWB + ks * 32 + ksel2;
                LDMATRIX_X4(bh[nt][0], bh[nt][1], bh[nt][2], bh[nt][3], ro);
            }
            #pragma unroll
            for (int nt = 0; nt < 4; nt++)
                #pragma unroll
                for (int h = 0; h < 2; h++)
                    MMA_F16(S[nt * 2 + h], qf[ks], bh[nt][h], bh[nt][h + 2]);
        }

        // ---- causal mask (diagonal subtile only) ----
        if (sglob == qt) {
            const int r0 = q0 + w * 16 + gr;
            #pragma unroll
            for (int f = 0; f < 8; f++) {
                const int c = q0 + f * 8 + gc2;
                if (c     > r0)     S[f][0] = -1e30f;
                if (c + 1 > r0)     S[f][1] = -1e30f;
                if (c     > r0 + 8) S[f][2] = -1e30f;
                if (c + 1 > r0 + 8) S[f][3] = -1e30f;
            }
        }

        // ---- online softmax (base 2) ----
        float mx0 = -1e30f, mx1 = -1e30f;
        #pragma unroll
        for (int f = 0; f < 8; f++) {
            mx0 = fmaxf(mx0, fmaxf(S[f][0], S[f][1]));
            mx1 = fmaxf(mx1, fmaxf(S[f][2], S[f][3]));
        }
        mx0 = fmaxf(mx0, __shfl_xor_sync(0xffffffffu, mx0, 1));
        mx0 = fmaxf(mx0, __shfl_xor_sync(0xffffffffu, mx0, 2));
        mx1 = fmaxf(mx1, __shfl_xor_sync(0xffffffffu, mx1, 1));
        mx1 = fmaxf(mx1, __shfl_xor_sync(0xffffffffu, mx1, 2));
        const float mn0 = fmaxf(m0, mx0), mn1 = fmaxf(m1, mx1);
        const float a0 = exp2f(m0 - mn0), a1 = exp2f(m1 - mn1);
        float s0 = 0.f, s1 = 0.f;
        #pragma unroll
        for (int f = 0; f < 8; f++) {
            S[f][0] = exp2f(S[f][0] - mn0);
            S[f][1] = exp2f(S[f][1] - mn0);
            S[f][2] = exp2f(S[f][2] - mn1);
            S[f][3] = exp2f(S[f][3] - mn1);
            s0 += S[f][0] + S[f][1];
            s1 += S[f][2] + S[f][3];
        }
        s0 += __shfl_xor_sync(0xffffffffu, s0, 1);
        s0 += __shfl_xor_sync(0xffffffffu, s0, 2);
        s1 += __shfl_xor_sync(0xffffffffu, s1, 1);
        s1 += __shfl_xor_sync(0xffffffffu, s1, 2);
        l0 = l0 * a0 + s0;
        l1 = l1 * a1 + s1;
        m0 = mn0; m1 = mn1;
        #pragma unroll
        for (int f = 0; f < 8; f++) {
            O[f][0] *= a0; O[f][1] *= a0;
            O[f][2] *= a1; O[f][3] *= a1;
        }

        // ---- O += P V (fp16 single, 1 pass); V via ldmatrix.trans ----
        #pragma unroll
        for (int ks = 0; ks < 4; ks++) {
            uint32_t pf[4];
            pf[0] = pack_h2(S[2 * ks][0],     S[2 * ks][1]);
            pf[1] = pack_h2(S[2 * ks][2],     S[2 * ks][3]);
            pf[2] = pack_h2(S[2 * ks + 1][0], S[2 * ks + 1][1]);
            pf[3] = pack_h2(S[2 * ks + 1][2], S[2 * ks + 1][3]);
            uint32_t vh[4][4];
            #pragma unroll
            for (int ht = 0; ht < 4; ht++) {
                uint32_t ro = kb + 9216u + (uint32_t)(ks * 16 + vkv) * ROWB + ht * 32 + vh16;
                LDMATRIX_X4_TRANS(vh[ht][0], vh[ht][1], vh[ht][2], vh[ht][3], ro);
            }
            #pragma unroll
            for (int ht = 0; ht < 4; ht++)
                #pragma unroll
                for (int h = 0; h < 2; h++)
                    MMA_F16(O[ht * 2 + h], pf, vh[ht][h], vh[ht][h + 2]);
        }

        __syncthreads();
        if (i + 2 < nsub) stage(sub0 + i + 2, i & 1);
    }

    // ---- epilogue: write partials (m in log2 units) ----
    {
        const size_t base = ((size_t)((b * QT_N + qt) * MAXCH + chunk)) * 4096;
        const int r0 = w * 16 + gr;
        #pragma unroll
        for (int f = 0; f < 8; f++) {
            const int h = f * 8 + gc2;
            *(float2*)&g_pO[base + (size_t)r0 * 64 + h]       = make_float2(O[f][0], O[f][1]);
            *(float2*)&g_pO[base + (size_t)(r0 + 8) * 64 + h] = make_float2(O[f][2], O[f][3]);
        }
        if ((lane & 3) == 0) {
            const size_t sbs = (size_t)((b * QT_N + qt) * MAXCH + chunk) * 64;
            g_pm[sbs + r0]     = m0;  g_pm[sbs + r0 + 8] = m1;
            g_pl[sbs + r0]     = l0;  g_pl[sbs + r0 + 8] = l1;
        }
    }
}

// ===========================================================================
// Kernel 3: combine partials -> final output (predicated prefetch, MLP=4)
// ===========================================================================
__global__ __launch_bounds__(256) void combine_kernel(float* __restrict__ out)
{
    int idx = blockIdx.x * 256 + threadIdx.x;
    int h4  = idx & 15;
    int q   = (Tseq - 1) - ((idx >> 4) & (Tseq - 1));   // heavy q rows first
    int b   = idx >> 15;
    int qt  = q >> 6;
    int row = q & 63;
    int nc  = (qt + CHSUB) >> 3;

    const size_t sbs = (size_t)(b * QT_N + qt) * MAXCH * 64 + row;
    const size_t ob  = (size_t)(b * QT_N + qt) * MAXCH * 4096 + (size_t)row * 64 + h4 * 4;

    float pm[MAXCH], pl[MAXCH];
    float4 p[MAXCH];
    #pragma unroll
    for (int c = 0; c < MAXCH; c++) {
        const bool v = c < nc;
        pm[c] = v ? g_pm[sbs + c * 64] : -1e30f;
        pl[c] = v ? g_pl[sbs + c * 64] : 0.f;
        p[c]  = v ? *(const float4*)&g_pO[ob + (size_t)c * 4096]
                  : make_float4(0.f, 0.f, 0.f, 0.f);
    }

    const float M = fmaxf(fmaxf(pm[0], pm[1]), fmaxf(pm[2], pm[3]));
    float L = 0.f, ox = 0.f, oy = 0.f, oz = 0.f, ow = 0.f;
    #pragma unroll
    for (int c = 0; c < MAXCH; c++) {
        const float wgt = exp2f(pm[c] - M);
        L += pl[c] * wgt;
        ox += wgt * p[c].x; oy += wgt * p[c].y;
        oz += wgt * p[c].z; ow += wgt * p[c].w;
    }
    const float inv = 1.0f / L;
    *(float4*)&out[((size_t)(b * Tseq + q)) * Hdim + h4 * 4] =
        make_float4(ox * inv, oy * inv, oz * inv, ow * inv);
}

// ===========================================================================
extern "C" void kernel_launch(void* const* d_in, const int* in_sizes, int n_in,
                              void* d_out, int out_size)
{
    const float* x  = (const float*)d_in[0];
    const float* wq = (const float*)d_in[1];
    const float* wk = (const float*)d_in[2];
    const float* wv = (const float*)d_in[3];
    float* out = (float*)d_out;

    cudaFuncSetAttribute(proj_mma_kernel, cudaFuncAttributeMaxDynamicSharedMemorySize,
                         PROJ_SMEM);
    cudaFuncSetAttribute(attn_mma_kernel, cudaFuncAttributeMaxDynamicSharedMemorySize,
                         ATTN_SMEM);

    pack_w_kernel<<<(192 * Cdim) / 256, 256>>>(wq, wk, wv);
    proj_mma_kernel<<<BT / 128, 256, PROJ_SMEM>>>(x);
    attn_mma_kernel<<<dim3(80, Bb), 128, ATTN_SMEM>>>();
    combine_kernel<<<(Bb * Tseq * 16) / 256, 256>>>(out);
}

// round 16
// speedup vs baseline: 2.3670x; 1.2733x over previous
#include <cuda_runtime.h>
#include <cuda_fp16.h>
#include <cstdint>

// Problem constants
#define Bb    8
#define Tseq  2048
#define Cdim  1024
#define Hdim  64
#define BT    (Bb * Tseq)
#define QSCALE (0.125f * 1.44269504089f)   // H^-0.5 * log2(e): base-2 softmax
#define QT_N  32      // number of 64-row q tiles per batch
#define CHSUB 8       // kv subtiles (of 64) per chunk
#define MAXCH 4       // max chunks per q tile

// Scratch (device globals — no allocation allowed)
__device__ __align__(128) __half g_qh[BT * Hdim];    // q, scaled, fp16
__device__ __align__(128) __half g_kh[BT * Hdim];    // k, fp16
__device__ __align__(128) __half g_vh[BT * Hdim];    // v, fp16
__device__ __align__(128) __half g_bw[192 * Cdim];   // packed weights, fp16
// attention partials
__device__ float g_pO[(size_t)Bb * QT_N * MAXCH * 64 * 64];
__device__ float g_pm[Bb * QT_N * MAXCH * 64];
__device__ float g_pl[Bb * QT_N * MAXCH * 64];

// ===========================================================================
// Generic-PTX tensor helpers (sm_80+ ISA)
// ===========================================================================
#define CP_ASYNC16(smem_u32, gptr) \
    asm volatile("cp.async.cg.shared.global [%0], [%1], 16;" \
                 :: "r"(smem_u32), "l"(gptr) : "memory")
#define CP_COMMIT() asm volatile("cp.async.commit_group;" ::: "memory")
#define CP_WAIT(N)  asm volatile("cp.async.wait_group %0;" :: "n"(N) : "memory")

#define LDMATRIX_X4(r0, r1, r2, r3, addr) \
    asm volatile("ldmatrix.sync.aligned.m8n8.x4.shared.b16 {%0,%1,%2,%3}, [%4];" \
                 : "=r"(r0), "=r"(r1), "=r"(r2), "=r"(r3) : "r"(addr))

#define LDMATRIX_X4_TRANS(r0, r1, r2, r3, addr) \
    asm volatile("ldmatrix.sync.aligned.m8n8.x4.trans.shared.b16 {%0,%1,%2,%3}, [%4];" \
                 : "=r"(r0), "=r"(r1), "=r"(r2), "=r"(r3) : "r"(addr))

// non-volatile — pure register op; data deps order it, ptxas may schedule
#define MMA_F16(d, a, b0, b1) \
    asm("mma.sync.aligned.m16n8k16.row.col.f32.f16.f16.f32 " \
        "{%0,%1,%2,%3}, {%4,%5,%6,%7}, {%8,%9}, {%0,%1,%2,%3};" \
        : "+f"((d)[0]), "+f"((d)[1]), "+f"((d)[2]), "+f"((d)[3]) \
        : "r"((a)[0]), "r"((a)[1]), "r"((a)[2]), "r"((a)[3]), \
          "r"(b0), "r"(b1))

__device__ __forceinline__ uint32_t smem_to_u32(const void* p) {
    uint32_t a;
    asm("{ .reg .u64 t; cvta.to.shared.u64 t, %1; cvt.u32.u64 %0, t; }" : "=r"(a) : "l"(p));
    return a;
}

__device__ __forceinline__ uint32_t pack_h2(float x, float y) {
    __half2 h2 = __halves2half2(__float2half(x), __float2half(y));
    return *(uint32_t*)&h2;
}

// ===========================================================================
// Kernel 0: pack weights into g_bw [192][1024] K-major (single fp16)
// ===========================================================================
__global__ __launch_bounds__(256) void pack_w_kernel(
    const float* __restrict__ wq, const float* __restrict__ wk, const float* __restrict__ wv)
{
    int idx = blockIdx.x * 256 + threadIdx.x;
    int n = idx >> 10;
    int k = idx & 1023;
    const float* w = (n < 64) ? wq : (n < 128) ? wk : wv;
    g_bw[idx] = __float2half(w[k * Hdim + (n & 63)]);
}

// ===========================================================================
// Kernel 1: projection GEMM, fp16 single-precision operands (1 pass).
// CTA tile 128m x 192n, 256 threads, grid=128. fp32 x cp.async'd raw and
// converted to fp16 in-kernel.
// ===========================================================================
#define ROWB144    144
#define AH_OFF     0                      // 2 x 18432
#define BW_OFF     36864                  // 2 x 27648
#define RAW_OFF    92160                  // 32768
#define PROJ_SMEM  124928
#define A_STG      18432
#define B_STG      27648
#define NCHUNK     (Cdim / 64)            // 16

__global__ __launch_bounds__(256, 1) void proj_mma_kernel(const float* __restrict__ x)
{
    extern __shared__ char smem[];
    const uint32_t sb = smem_to_u32(smem);
    const int tid  = threadIdx.x;
    const int wid  = tid >> 5;
    const int lane = tid & 31;
    const int row0 = blockIdx.x * 128;

    const int wm = wid >> 2;
    const int wn = wid & 3;

    float acc[4][6][4];
    #pragma unroll
    for (int i = 0; i < 4; i++)
        #pragma unroll
        for (int j = 0; j < 6; j++)
            #pragma unroll
            for (int r = 0; r < 4; r++) acc[i][j][r] = 0.f;

    auto issue_chunk = [&](int c) {
        const int k0 = c * 64;
        const int s  = c & 1;
        // raw x: 128 rows x 256 B -> 2048 16B segs, 8/thread
        #pragma unroll
        for (int t = 0; t < 8; t++) {
            int seg = tid + t * 256;
            int r = seg >> 4, o = seg & 15;
            CP_ASYNC16(sb + RAW_OFF + r * 256 + o * 16,
                       &x[(size_t)(row0 + r) * Cdim + k0 + o * 4]);
        }
        // B (fp16): 192 rows x 128 B -> 1536 segs, 6/thread
        #pragma unroll
        for (int t = 0; t < 6; t++) {
            int seg = tid + t * 256;
            int r = seg >> 3, o8 = seg & 7;
            CP_ASYNC16(sb + BW_OFF + s * B_STG + r * ROWB144 + o8 * 16,
                       &g_bw[(size_t)r * Cdim + k0 + o8 * 8]);
        }
        CP_COMMIT();
    };

    issue_chunk(0);

    const int rsel = lane & 15;
    const int ksel = (lane < 16) ? 0 : 8;

    for (int c = 0; c < NCHUNK; c++) {
        const int s = c & 1;
        CP_WAIT(0);
        __syncthreads();

        // convert raw fp32 -> A (fp16) stage s  (8 float4 per thread)
        #pragma unroll
        for (int t = 0; t < 8; t++) {
            int seg = tid + t * 256;          // 0..2047
            int r = seg >> 4, kp = seg & 15;
            float4 v = *(const float4*)(smem + RAW_OFF + r * 256 + kp * 16);
            uint32_t h0 = pack_h2(v.x, v.y);
            uint32_t h1 = pack_h2(v.z, v.w);
            asm volatile("st.shared.v2.b32 [%0], {%1, %2};"
                         :: "r"(sb + AH_OFF + s * A_STG + r * ROWB144 + kp * 8),
                            "r"(h0), "r"(h1) : "memory");
        }
        __syncthreads();                       // A visible; raw buffer free

        if (c + 1 < NCHUNK) issue_chunk(c + 1);

        const uint32_t Ah = sb + AH_OFF + s * A_STG;
        const uint32_t Bw = sb + BW_OFF + s * B_STG;

        #pragma unroll
        for (int kk = 0; kk < 4; kk++) {
            const uint32_t kb = (kk * 16 + ksel) * 2;
            uint32_t ah[4][4];
            #pragma unroll
            for (int i = 0; i < 4; i++) {
                uint32_t ro = (uint32_t)(wm * 64 + i * 16 + rsel) * ROWB144 + kb;
                LDMATRIX_X4(ah[i][0], ah[i][1], ah[i][2], ah[i][3], Ah + ro);
            }
            uint32_t bw[3][4];
            #pragma unroll
            for (int p = 0; p < 3; p++) {
                uint32_t ro = (uint32_t)(wn * 48 + p * 16 + rsel) * ROWB144 + kb;
                LDMATRIX_X4(bw[p][0], bw[p][1], bw[p][2], bw[p][3], Bw + ro);
            }
            // single pass: 24 independent MMAs
            #pragma unroll
            for (int i = 0; i < 4; i++)
                #pragma unroll
                for (int p = 0; p < 3; p++)
                    #pragma unroll
                    for (int h = 0; h < 2; h++)
                        MMA_F16(acc[i][p * 2 + h], ah[i], bw[p][h], bw[p][h + 2]);
        }
        __syncthreads();
    }

    // Epilogue: q -> scaled fp16; k -> fp16; v -> fp16
    #pragma unroll
    for (int i = 0; i < 4; i++) {
        const int rA = row0 + wm * 64 + i * 16 + (lane >> 2);
        #pragma unroll
        for (int j = 0; j < 6; j++) {
            const int col = wn * 48 + j * 8 + (lane & 3) * 2;
            float v00 = acc[i][j][0], v01 = acc[i][j][1];
            float v10 = acc[i][j][2], v11 = acc[i][j][3];
            const int h = col & 63;
            size_t o0 = (size_t)rA * Hdim + h;
            size_t o1 = (size_t)(rA + 8) * Hdim + h;
            if (col < 64) {
                *(uint32_t*)&g_qh[o0] = pack_h2(v00 * QSCALE, v01 * QSCALE);
                *(uint32_t*)&g_qh[o1] = pack_h2(v10 * QSCALE, v11 * QSCALE);
            } else if (col < 128) {
                *(uint32_t*)&g_kh[o0] = pack_h2(v00, v01);
                *(uint32_t*)&g_kh[o1] = pack_h2(v10, v11);
            } else {
                *(uint32_t*)&g_vh[o0] = pack_h2(v00, v01);
                *(uint32_t*)&g_vh[o1] = pack_h2(v10, v11);
            }
        }
    }
}

// ===========================================================================
// Kernel 2: flash-attention on mma.sync fp16, single-precision operands
// (1 pass per GEMM), base-2 softmax.
// ===========================================================================
#define ROWB   144
#define QF_OFF 0                            // 9216 (single Q)
#define STG_OFF 9216
#define STG_SZ  18432                       // Kh | Vh (9216 each)
#define ATTN_SMEM (STG_OFF + 2 * STG_SZ)    // 46080

__global__ __launch_bounds__(128) void attn_mma_kernel()
{
    extern __shared__ char smem[];
    const uint32_t sb = smem_to_u32(smem);
    const int tid  = threadIdx.x;
    const int w    = tid >> 5;
    const int lane = tid & 31;
    const int b    = blockIdx.y;

    // map blockIdx.x -> (qt, chunk), heavy qtiles first
    int u = blockIdx.x, qt = QT_N - 1, chunk = 0;
    for (;;) {
        int nc = (qt + CHSUB) >> 3;
        if (u < nc) { chunk = u; break; }
        u -= nc; qt--;
    }
    const int nsub = min(CHSUB, (qt + 1) - chunk * CHSUB);
    const int sub0 = chunk * CHSUB;
    const int q0   = qt * 64;

    // ---- stage Q (single fp16) ----
    {
        const __half* qp = g_qh + ((size_t)(b * Tseq + q0)) * Hdim;
        #pragma unroll
        for (int t = 0; t < 4; t++) {
            int seg = tid + t * 128;          // 0..511
            int r = seg >> 3, o = seg & 7;
            CP_ASYNC16(sb + QF_OFF + r * ROWB + o * 16, qp + r * 64 + o * 8);
        }
        CP_COMMIT();
    }

    auto stage = [&](int s, int buf) {
        const uint32_t o = sb + STG_OFF + (uint32_t)buf * STG_SZ;
        const size_t gbase = ((size_t)(b * Tseq + s * 64)) * Hdim;
        #pragma unroll
        for (int t = 0; t < 4; t++) {
            int seg = tid + t * 128;
            int r = seg >> 3, c = seg & 7;
            size_t ge = gbase + r * 64 + c * 8;
            CP_ASYNC16(o + r * ROWB + c * 16,        &g_kh[ge]);
            CP_ASYNC16(o + 9216 + r * ROWB + c * 16, &g_vh[ge]);
        }
        CP_COMMIT();
    };

    stage(sub0, 0);
    if (nsub > 1) stage(sub0 + 1, 1);

    const int rsel  = lane & 15;
    const int ksel2 = (lane < 16) ? 0 : 16;
    const int vkv  = ((lane >> 4) & 1) * 8 + (lane & 7);
    const int vh16 = ((lane >> 3) & 1) * 16;

    if (nsub > 1) { CP_WAIT(1); } else { CP_WAIT(0); }
    __syncthreads();

    uint32_t qf[4][4];
    #pragma unroll
    for (int ks = 0; ks < 4; ks++) {
        uint32_t ro = sb + QF_OFF + (uint32_t)(w * 16 + rsel) * ROWB + ks * 32 + ksel2;
        LDMATRIX_X4(qf[ks][0], qf[ks][1], qf[ks][2], qf[ks][3], ro);
    }

    float m0 = -1e30f, m1 = -1e30f, l0 = 0.f, l1 = 0.f;
    float O[8][4];
    #pragma unroll
    for (int f = 0; f < 8; f++)
        #pragma unroll
        for (int r = 0; r < 4; r++) O[f][r] = 0.f;

    const int gr  = lane >> 2;
    const int gc2 = (lane & 3) * 2;

    for (int i = 0; i < nsub; i++) {
        if (i > 0) {
            if (i + 1 < nsub) CP_WAIT(1); else CP_WAIT(0);
            __syncthreads();
        }
        const uint32_t kb = sb + STG_OFF + (uint32_t)(i & 1) * STG_SZ;
        const int sglob = sub0 + i;

        // ---- S = Q K^T (fp16 single, 1 pass) ----
        float S[8][4];
        #pragma unroll
        for (int f = 0; f < 8; f++)
            #pragma unroll
            for (int r = 0; r < 4; r++) S[f][r] = 0.f;

        #pragma unroll
        for (int ks = 0; ks < 4; ks++) {
            uint32_t bh[4][4];
            #pragma unroll
            for (int nt = 0; nt < 4; nt++) {
                uint32_t ro = kb + (uint32_t)(nt * 16 + rsel) * ROWB + ks * 32 + ksel2;
                LDMATRIX_X4(bh[nt][0], bh[nt][1], bh[nt][2], bh[nt][3], ro);
            }
            #pragma unroll
            for (int nt = 0; nt < 4; nt++)
                #pragma unroll
                for (int h = 0; h < 2; h++)
                    MMA_F16(S[nt * 2 + h], qf[ks], bh[nt][h], bh[nt][h + 2]);
        }

        // ---- causal mask (diagonal subtile only) ----
        if (sglob == qt) {
            const int r0 = q0 + w * 16 + gr;
            #pragma unroll
            for (int f = 0; f < 8; f++) {
                const int c = q0 + f * 8 + gc2;
                if (c     > r0)     S[f][0] = -1e30f;
                if (c + 1 > r0)     S[f][1] = -1e30f;
                if (c     > r0 + 8) S[f][2] = -1e30f;
                if (c + 1 > r0 + 8) S[f][3] = -1e30f;
            }
        }

        // ---- online softmax (base 2) ----
        float mx0 = -1e30f, mx1 = -1e30f;
        #pragma unroll
        for (int f = 0; f < 8; f++) {
            mx0 = fmaxf(mx0, fmaxf(S[f][0], S[f][1]));
            mx1 = fmaxf(mx1, fmaxf(S[f][2], S[f][3]));
        }
        mx0 = fmaxf(mx0, __shfl_xor_sync(0xffffffffu, mx0, 1));
        mx0 = fmaxf(mx0, __shfl_xor_sync(0xffffffffu, mx0, 2));
        mx1 = fmaxf(mx1, __shfl_xor_sync(0xffffffffu, mx1, 1));
        mx1 = fmaxf(mx1, __shfl_xor_sync(0xffffffffu, mx1, 2));
        const float mn0 = fmaxf(m0, mx0), mn1 = fmaxf(m1, mx1);
        const float a0 = exp2f(m0 - mn0), a1 = exp2f(m1 - mn1);
        float s0 = 0.f, s1 = 0.f;
        #pragma unroll
        for (int f = 0; f < 8; f++) {
            S[f][0] = exp2f(S[f][0] - mn0);
            S[f][1] = exp2f(S[f][1] - mn0);
            S[f][2] = exp2f(S[f][2] - mn1);
            S[f][3] = exp2f(S[f][3] - mn1);
            s0 += S[f][0] + S[f][1];
            s1 += S[f][2] + S[f][3];
        }
        s0 += __shfl_xor_sync(0xffffffffu, s0, 1);
        s0 += __shfl_xor_sync(0xffffffffu, s0, 2);
        s1 += __shfl_xor_sync(0xffffffffu, s1, 1);
        s1 += __shfl_xor_sync(0xffffffffu, s1, 2);
        l0 = l0 * a0 + s0;
        l1 = l1 * a1 + s1;
        m0 = mn0; m1 = mn1;
        #pragma unroll
        for (int f = 0; f < 8; f++) {
            O[f][0] *= a0; O[f][1] *= a0;
            O[f][2] *= a1; O[f][3] *= a1;
        }

        // ---- O += P V (fp16 single, 1 pass); V via ldmatrix.trans ----
        #pragma unroll
        for (int ks = 0; ks < 4; ks++) {
            uint32_t pf[4];
            pf[0] = pack_h2(S[2 * ks][0],     S[2 * ks][1]);
            pf[1] = pack_h2(S[2 * ks][2],     S[2 * ks][3]);
            pf[2] = pack_h2(S[2 * ks + 1][0], S[2 * ks + 1][1]);
            pf[3] = pack_h2(S[2 * ks + 1][2], S[2 * ks + 1][3]);
            uint32_t vh[4][4];
            #pragma unroll
            for (int ht = 0; ht < 4; ht++) {
                uint32_t ro = kb + 9216u + (uint32_t)(ks * 16 + vkv) * ROWB + ht * 32 + vh16;
                LDMATRIX_X4_TRANS(vh[ht][0], vh[ht][1], vh[ht][2], vh[ht][3], ro);
            }
            #pragma unroll
            for (int ht = 0; ht < 4; ht++)
                #pragma unroll
                for (int h = 0; h < 2; h++)
                    MMA_F16(O[ht * 2 + h], pf, vh[ht][h], vh[ht][h + 2]);
        }

        __syncthreads();
        if (i + 2 < nsub) stage(sub0 + i + 2, i & 1);
    }

    // ---- epilogue: write partials (m in log2 units) ----
    {
        const size_t base = ((size_t)((b * QT_N + qt) * MAXCH + chunk)) * 4096;
        const int r0 = w * 16 + gr;
        #pragma unroll
        for (int f = 0; f < 8; f++) {
            const int h = f * 8 + gc2;
            *(float2*)&g_pO[base + (size_t)r0 * 64 + h]       = make_float2(O[f][0], O[f][1]);
            *(float2*)&g_pO[base + (size_t)(r0 + 8) * 64 + h] = make_float2(O[f][2], O[f][3]);
        }
        if ((lane & 3) == 0) {
            const size_t sbs = (size_t)((b * QT_N + qt) * MAXCH + chunk) * 64;
            g_pm[sbs + r0]     = m0;  g_pm[sbs + r0 + 8] = m1;
            g_pl[sbs + r0]     = l0;  g_pl[sbs + r0 + 8] = l1;
        }
    }
}

// ===========================================================================
// Kernel 3: combine partials -> final output (predicated prefetch, MLP=4)
// ===========================================================================
__global__ __launch_bounds__(256) void combine_kernel(float* __restrict__ out)
{
    int idx = blockIdx.x * 256 + threadIdx.x;
    int h4  = idx & 15;
    int q   = (Tseq - 1) - ((idx >> 4) & (Tseq - 1));   // heavy q rows first
    int b   = idx >> 15;
    int qt  = q >> 6;
    int row = q & 63;
    int nc  = (qt + CHSUB) >> 3;

    const size_t sbs = (size_t)(b * QT_N + qt) * MAXCH * 64 + row;
    const size_t ob  = (size_t)(b * QT_N + qt) * MAXCH * 4096 + (size_t)row * 64 + h4 * 4;

    float pm[MAXCH], pl[MAXCH];
    float4 p[MAXCH];
    #pragma unroll
    for (int c = 0; c < MAXCH; c++) {
        const bool v = c < nc;
        pm[c] = v ? g_pm[sbs + c * 64] : -1e30f;
        pl[c] = v ? g_pl[sbs + c * 64] : 0.f;
        p[c]  = v ? *(const float4*)&g_pO[ob + (size_t)c * 4096]
                  : make_float4(0.f, 0.f, 0.f, 0.f);
    }

    const float M = fmaxf(fmaxf(pm[0], pm[1]), fmaxf(pm[2], pm[3]));
    float L = 0.f, ox = 0.f, oy = 0.f, oz = 0.f, ow = 0.f;
    #pragma unroll
    for (int c = 0; c < MAXCH; c++) {
        const float wgt = exp2f(pm[c] - M);
        L += pl[c] * wgt;
        ox += wgt * p[c].x; oy += wgt * p[c].y;
        oz += wgt * p[c].z; ow += wgt * p[c].w;
    }
    const float inv = 1.0f / L;
    *(float4*)&out[((size_t)(b * Tseq + q)) * Hdim + h4 * 4] =
        make_float4(ox * inv, oy * inv, oz * inv, ow * inv);
}

// ===========================================================================
extern "C" void kernel_launch(void* const* d_in, const int* in_sizes, int n_in,
                              void* d_out, int out_size)
{
    const float* x  = (const float*)d_in[0];
    const float* wq = (const float*)d_in[1];
    const float* wk = (const float*)d_in[2];
    const float* wv = (const float*)d_in[3];
    float* out = (float*)d_out;

    cudaFuncSetAttribute(proj_mma_kernel, cudaFuncAttributeMaxDynamicSharedMemorySize,
                         PROJ_SMEM);
    cudaFuncSetAttribute(attn_mma_kernel, cudaFuncAttributeMaxDynamicSharedMemorySize,
                         ATTN_SMEM);

    pack_w_kernel<<<(192 * Cdim) / 256, 256>>>(wq, wk, wv);
    proj_mma_kernel<<<BT / 128, 256, PROJ_SMEM>>>(x);
    attn_mma_kernel<<<dim3(80, Bb), 128, ATTN_SMEM>>>();
    combine_kernel<<<(Bb * Tseq * 16) / 256, 256>>>(out);
}